// round 3
// baseline (speedup 1.0000x reference)
#include <cuda_runtime.h>
#include <math.h>

#define NPATH 100000
#define NLINK 20000
#define TMAX 8
#define NDEG 48
#define DS 64
#define NITERS 4

// Persistent scratch: uninitialized __device__ globals (no payload in cubin,
// no runtime allocation, referenced directly from device code).
__device__ float g_path_state[NPATH * DS];                 // [P,64]
__device__ float g_link_state[NLINK * DS];                 // [L,64]
__device__ float g_pss[NPATH * (TMAX + 1) * DS];           // [P,9,64]
__device__ float g_agg[NLINK * 4 * DS];                    // [L,256]
__device__ float g_t1[NLINK * 128];
__device__ float g_t2[NLINK * 128];
__device__ float g_pa[NLINK * DS];

__device__ __forceinline__ void groupbar(int g) {
    asm volatile("bar.sync %0, 64;" :: "r"(g + 1) : "memory");
}
__device__ __forceinline__ float sigm(float x) { return 1.0f / (1.0f + expf(-x)); }

// ---------------------------------------------------------------------------
// Embedding: st[p,d] = relu( relu(x[p]*w1[d]+b1[d]) @ w2^T + b2 )
// TARGET=0 -> g_path_state, TARGET=1 -> g_link_state.
// block 256 = 4 groups of 64 threads; each group one row per pass.
// ---------------------------------------------------------------------------
template <int TARGET>
__global__ void embed_kernel(const float* __restrict__ x,
                             const float* __restrict__ w1, const float* __restrict__ b1,
                             const float* __restrict__ w2, const float* __restrict__ b2,
                             int n) {
    __shared__ float sW[64 * 64];     // transposed: sW[k*64 + j] = w2[j*64 + k]
    __shared__ float sw1[64], sb1[64], sb2[64];
    __shared__ float sh1[4][64];
    float* st = (TARGET == 0) ? g_path_state : g_link_state;
    int tid = threadIdx.x;
    for (int i = tid; i < 4096; i += 256) {
        int j = i >> 6, k = i & 63;
        sW[k * 64 + j] = w2[i];
    }
    if (tid < 64) { sw1[tid] = w1[tid]; sb1[tid] = b1[tid]; sb2[tid] = b2[tid]; }
    __syncthreads();
    int g = tid >> 6, d = tid & 63;
    for (int base = blockIdx.x * 4; base < n; base += gridDim.x * 4) {
        int p = base + g;
        float h1 = 0.0f;
        if (p < n) {
            float t = x[p];
            h1 = fmaxf(t * sw1[d] + sb1[d], 0.0f);
        }
        sh1[g][d] = h1;
        groupbar(g);
        float acc = sb2[d];
#pragma unroll 8
        for (int k = 0; k < 64; k++) acc += sh1[g][k] * sW[k * 64 + d];
        if (p < n) st[p * 64 + d] = fmaxf(acc, 0.0f);
        groupbar(g);
    }
}

// ---------------------------------------------------------------------------
// Path GRU over packed sequences. block 256 = 4 groups x 64 threads.
// Each group processes 2 paths concurrently (weight LDS amortized 2x).
// Writes pss[p,0]=h0, pss[p,t+1]=h_t (zeros past length), path_state=h_final.
// ---------------------------------------------------------------------------
__global__ void gru_path_kernel(const int* __restrict__ l2p,
                                const float* __restrict__ wih, const float* __restrict__ whh,
                                const float* __restrict__ bih, const float* __restrict__ bhh) {
    extern __shared__ float sm[];
    float* sWi = sm;                   // [64][192], sWi[k*192+j] = wih[j*64+k]
    float* sWh = sWi + 64 * 192;
    float* sbi = sWh + 64 * 192;       // 192
    float* sbh = sbi + 192;            // 192
    float* sx  = sbh + 192;            // [4][2][64]
    float* sh  = sx + 4 * 2 * 64;      // [4][2][64]
    int tid = threadIdx.x;
    for (int i = tid; i < 192 * 64; i += 256) {
        int j = i / 64, k = i % 64;
        sWi[k * 192 + j] = wih[i];
        sWh[k * 192 + j] = whh[i];
    }
    for (int i = tid; i < 192; i += 256) { sbi[i] = bih[i]; sbh[i] = bhh[i]; }
    __syncthreads();

    int g = tid >> 6, d = tid & 63;
    float* gx = sx + g * 128;
    float* gh = sh + g * 128;

    for (int base = blockIdx.x * 8; base < NPATH; base += gridDim.x * 8) {
        int p0 = base + g * 2, p1 = p0 + 1;
        bool e0 = p0 < NPATH, e1 = p1 < NPATH;
        int len0 = 0, len1 = 0;
        if (e0) {
#pragma unroll
            for (int t = 0; t < TMAX; t++) len0 += (l2p[p0 * TMAX + t] != -1) ? 1 : 0;
        }
        if (e1) {
#pragma unroll
            for (int t = 0; t < TMAX; t++) len1 += (l2p[p1 * TMAX + t] != -1) ? 1 : 0;
        }
        float h0d = 0.0f, h1d = 0.0f;
        if (e0) { h0d = g_path_state[p0 * 64 + d]; g_pss[p0 * 576 + d] = h0d; }
        if (e1) { h1d = g_path_state[p1 * 64 + d]; g_pss[p1 * 576 + d] = h1d; }
        gx[d] = 0.0f; gx[64 + d] = 0.0f;
        gh[d] = h0d;  gh[64 + d] = h1d;
        int lenm = len0 > len1 ? len0 : len1;
        groupbar(g);

        for (int t = 0; t < lenm; t++) {
            bool v0 = t < len0, v1 = t < len1;
            if (v0) { int lk = l2p[p0 * TMAX + t]; gx[d]      = g_link_state[lk * 64 + d]; }
            if (v1) { int lk = l2p[p1 * TMAX + t]; gx[64 + d] = g_link_state[lk * 64 + d]; }
            groupbar(g);
            float a0r = sbi[d], a0z = sbi[64 + d], a0n = sbi[128 + d];
            float c0r = sbh[d], c0z = sbh[64 + d], c0n = sbh[128 + d];
            float a1r = a0r, a1z = a0z, a1n = a0n;
            float c1r = c0r, c1z = c0z, c1n = c0n;
#pragma unroll 8
            for (int k = 0; k < 64; k++) {
                float x0 = gx[k], x1 = gx[64 + k];
                float q0 = gh[k], q1 = gh[64 + k];
                const float* wi = sWi + k * 192;
                const float* wh = sWh + k * 192;
                float wr = wi[d], wz = wi[64 + d], wn = wi[128 + d];
                float vr = wh[d], vz = wh[64 + d], vn = wh[128 + d];
                a0r += x0 * wr; a1r += x1 * wr;
                a0z += x0 * wz; a1z += x1 * wz;
                a0n += x0 * wn; a1n += x1 * wn;
                c0r += q0 * vr; c1r += q1 * vr;
                c0z += q0 * vz; c1z += q1 * vz;
                c0n += q0 * vn; c1n += q1 * vn;
            }
            groupbar(g);
            if (v0) {
                float r = sigm(a0r + c0r);
                float z = sigm(a0z + c0z);
                float nn = tanhf(a0n + r * c0n);
                h0d = (1.0f - z) * nn + z * h0d;
                gh[d] = h0d;
                g_pss[p0 * 576 + (t + 1) * 64 + d] = h0d;
            }
            if (v1) {
                float r = sigm(a1r + c1r);
                float z = sigm(a1z + c1z);
                float nn = tanhf(a1n + r * c1n);
                h1d = (1.0f - z) * nn + z * h1d;
                gh[64 + d] = h1d;
                g_pss[p1 * 576 + (t + 1) * 64 + d] = h1d;
            }
        }
        for (int t = len0; t < TMAX; t++) if (e0) g_pss[p0 * 576 + (t + 1) * 64 + d] = 0.0f;
        for (int t = len1; t < TMAX; t++) if (e1) g_pss[p1 * 576 + (t + 1) * 64 + d] = 0.0f;
        if (e0) g_path_state[p0 * 64 + d] = h0d;
        if (e1) g_path_state[p1 * 64 + d] = h1d;
        groupbar(g);
    }
}

// ---------------------------------------------------------------------------
// Link aggregation: agg[l] = [min | max | sum | mean] over valid (path,pos).
// block 256 = 4 groups x 64 threads; group per link.
// ---------------------------------------------------------------------------
__global__ void agg_kernel(const int* __restrict__ p2l) {
    __shared__ int s_pi[4][NDEG], s_pos[4][NDEG];
    int tid = threadIdx.x;
    int g = tid >> 6, d = tid & 63;
    for (int base = blockIdx.x * 4; base < NLINK; base += gridDim.x * 4) {
        int l = base + g;
        if (l < NLINK && d < NDEG) {
            s_pi[g][d]  = p2l[(l * NDEG + d) * 2];
            s_pos[g][d] = p2l[(l * NDEG + d) * 2 + 1];
        }
        groupbar(g);
        if (l < NLINK) {
            float vmin = INFINITY, vmax = -INFINITY, vsum = 0.0f;
            int cnt = 0;
            for (int e = 0; e < NDEG; e++) {
                int pi = s_pi[g][e];
                if (pi < 0) continue;
                cnt++;
                float v = g_pss[(pi * 9 + s_pos[g][e]) * 64 + d];
                vmin = fminf(vmin, v);
                vmax = fmaxf(vmax, v);
                vsum += v;
            }
            float mean = vsum / (float)(cnt > 0 ? cnt : 1);
            g_agg[l * 256 + d]        = vmin;
            g_agg[l * 256 + 64 + d]   = vmax;
            g_agg[l * 256 + 128 + d]  = vsum;
            g_agg[l * 256 + 192 + d]  = mean;
        }
        groupbar(g);
    }
}

// ---------------------------------------------------------------------------
// Batched matvec + relu: out[l,j] = relu(sum_k in[l,k]*W[j,k] + b[j])
// blockDim = OUT; NL rows per pass; transposed weights in SMEM.
// SRC/DST select device-global buffers: 0=g_agg,1=g_t1,2=g_t2,3=g_pa.
// ---------------------------------------------------------------------------
__device__ __forceinline__ float* buf_sel(int s) {
    if (s == 0) return g_agg;
    if (s == 1) return g_t1;
    if (s == 2) return g_t2;
    return g_pa;
}

template <int IN, int OUT, int NL, int SRC, int DST>
__global__ void matvec_relu(const float* __restrict__ W,
                            const float* __restrict__ b, int n) {
    extern __shared__ float sm[];
    float* sWT = sm;             // [IN][OUT]
    float* sb  = sWT + IN * OUT; // OUT
    float* sin = sb + OUT;       // NL*IN
    const float* in = buf_sel(SRC);
    float* out = buf_sel(DST);
    int tid = threadIdx.x;
    for (int i = tid; i < IN * OUT; i += OUT) {
        int j = i / IN, k = i % IN;
        sWT[k * OUT + j] = W[i];
    }
    if (tid < OUT) sb[tid] = b[tid];
    __syncthreads();
    for (int l0 = blockIdx.x * NL; l0 < n; l0 += gridDim.x * NL) {
        for (int i = tid; i < NL * IN; i += OUT) {
            int ll = l0 + i / IN;
            sin[i] = (ll < n) ? in[ll * IN + (i % IN)] : 0.0f;
        }
        __syncthreads();
        float acc[NL];
#pragma unroll
        for (int q = 0; q < NL; q++) acc[q] = sb[tid];
#pragma unroll 4
        for (int k = 0; k < IN; k++) {
            float w = sWT[k * OUT + tid];
#pragma unroll
            for (int q = 0; q < NL; q++) acc[q] += sin[q * IN + k] * w;
        }
#pragma unroll
        for (int q = 0; q < NL; q++) {
            int ll = l0 + q;
            if (ll < n) out[ll * OUT + tid] = fmaxf(acc[q], 0.0f);
        }
        __syncthreads();
    }
}

// ---------------------------------------------------------------------------
// Link GRU cell (single step, in-place on g_link_state). Input = g_pa.
// block 256 = 4 groups x 64 threads; group per link.
// ---------------------------------------------------------------------------
__global__ void gru_link_kernel(const float* __restrict__ wih, const float* __restrict__ whh,
                                const float* __restrict__ bih, const float* __restrict__ bhh) {
    extern __shared__ float sm[];
    float* sWi = sm;
    float* sWh = sWi + 64 * 192;
    float* sbi = sWh + 64 * 192;
    float* sbh = sbi + 192;
    float* sx  = sbh + 192;       // [4][64]
    float* sh  = sx + 4 * 64;     // [4][64]
    int tid = threadIdx.x;
    for (int i = tid; i < 192 * 64; i += 256) {
        int j = i / 64, k = i % 64;
        sWi[k * 192 + j] = wih[i];
        sWh[k * 192 + j] = whh[i];
    }
    for (int i = tid; i < 192; i += 256) { sbi[i] = bih[i]; sbh[i] = bhh[i]; }
    __syncthreads();
    int g = tid >> 6, d = tid & 63;
    float* gx = sx + g * 64;
    float* gh = sh + g * 64;
    for (int base = blockIdx.x * 4; base < NLINK; base += gridDim.x * 4) {
        int l = base + g;
        bool e = l < NLINK;
        float hd = 0.0f;
        if (e) {
            gx[d] = g_pa[l * 64 + d];
            hd = g_link_state[l * 64 + d];
            gh[d] = hd;
        } else { gx[d] = 0.0f; gh[d] = 0.0f; }
        groupbar(g);
        float ar = sbi[d], az = sbi[64 + d], an = sbi[128 + d];
        float cr = sbh[d], cz = sbh[64 + d], cn = sbh[128 + d];
#pragma unroll 8
        for (int k = 0; k < 64; k++) {
            float xk = gx[k], hk = gh[k];
            const float* wi = sWi + k * 192;
            const float* wh = sWh + k * 192;
            ar += xk * wi[d];       az += xk * wi[64 + d];  an += xk * wi[128 + d];
            cr += hk * wh[d];       cz += hk * wh[64 + d];  cn += hk * wh[128 + d];
        }
        groupbar(g);
        if (e) {
            float r = sigm(ar + cr);
            float z = sigm(az + cz);
            float nn = tanhf(an + r * cn);
            g_link_state[l * 64 + d] = (1.0f - z) * nn + z * hd;
        }
        groupbar(g);
    }
}

// ---------------------------------------------------------------------------
// Output copy: [path_state | link_state]
// ---------------------------------------------------------------------------
__global__ void copy_out_kernel(float* __restrict__ out, int out_size) {
    const int n1 = NPATH * DS;
    const int n2 = n1 + NLINK * DS;
    for (int i = blockIdx.x * blockDim.x + threadIdx.x; i < out_size;
         i += gridDim.x * blockDim.x) {
        float v = 0.0f;
        if (i < n1) v = g_path_state[i];
        else if (i < n2) v = g_link_state[i - n1];
        out[i] = v;
    }
}

extern "C" void kernel_launch(void* const* d_in, const int* in_sizes, int n_in,
                              void* d_out, int out_size) {
    const float* traffic   = (const float*)d_in[0];
    const float* capacity  = (const float*)d_in[1];
    const int*   l2p       = (const int*)d_in[2];
    const int*   p2l       = (const int*)d_in[3];
    const float* pe_w1 = (const float*)d_in[4];
    const float* pe_b1 = (const float*)d_in[5];
    const float* pe_w2 = (const float*)d_in[6];
    const float* pe_b2 = (const float*)d_in[7];
    const float* le_w1 = (const float*)d_in[8];
    const float* le_b1 = (const float*)d_in[9];
    const float* le_w2 = (const float*)d_in[10];
    const float* le_b2 = (const float*)d_in[11];
    const float* gru_wih = (const float*)d_in[12];
    const float* gru_whh = (const float*)d_in[13];
    const float* gru_bih = (const float*)d_in[14];
    const float* gru_bhh = (const float*)d_in[15];
    const float* cell_wih = (const float*)d_in[16];
    const float* cell_whh = (const float*)d_in[17];
    const float* cell_bih = (const float*)d_in[18];
    const float* cell_bhh = (const float*)d_in[19];
    const float* am_w1 = (const float*)d_in[20];
    const float* am_b1 = (const float*)d_in[21];
    const float* am_w2 = (const float*)d_in[22];
    const float* am_b2 = (const float*)d_in[23];
    const float* am_w3 = (const float*)d_in[24];
    const float* am_b3 = (const float*)d_in[25];

    const size_t smem_gru  = (size_t)(2 * 64 * 192 + 2 * 192 + 2 * 4 * 2 * 64) * 4;
    const size_t smem_grul = (size_t)(2 * 64 * 192 + 2 * 192 + 2 * 4 * 64) * 4;
    const size_t smem_l1 = (size_t)(256 * 128 + 128 + 4 * 256) * 4;
    const size_t smem_l2 = (size_t)(128 * 128 + 128 + 4 * 128) * 4;
    const size_t smem_l3 = (size_t)(128 * 64 + 64 + 4 * 128) * 4;

    cudaFuncSetAttribute(gru_path_kernel, cudaFuncAttributeMaxDynamicSharedMemorySize, (int)smem_gru);
    cudaFuncSetAttribute(gru_link_kernel, cudaFuncAttributeMaxDynamicSharedMemorySize, (int)smem_grul);
    cudaFuncSetAttribute(matvec_relu<256, 128, 4, 0, 1>, cudaFuncAttributeMaxDynamicSharedMemorySize, (int)smem_l1);
    cudaFuncSetAttribute(matvec_relu<128, 128, 4, 1, 2>, cudaFuncAttributeMaxDynamicSharedMemorySize, (int)smem_l2);
    cudaFuncSetAttribute(matvec_relu<128, 64, 4, 2, 3>,  cudaFuncAttributeMaxDynamicSharedMemorySize, (int)smem_l3);

    embed_kernel<0><<<1024, 256>>>(traffic, pe_w1, pe_b1, pe_w2, pe_b2, NPATH);
    embed_kernel<1><<<512, 256>>>(capacity, le_w1, le_b1, le_w2, le_b2, NLINK);

    for (int it = 0; it < NITERS; it++) {
        gru_path_kernel<<<296, 256, smem_gru>>>(l2p, gru_wih, gru_whh, gru_bih, gru_bhh);
        agg_kernel<<<1024, 256>>>(p2l);
        matvec_relu<256, 128, 4, 0, 1><<<296, 128, smem_l1>>>(am_w1, am_b1, NLINK);
        matvec_relu<128, 128, 4, 1, 2><<<296, 128, smem_l2>>>(am_w2, am_b2, NLINK);
        matvec_relu<128, 64, 4, 2, 3><<<296, 64, smem_l3>>>(am_w3, am_b3, NLINK);
        gru_link_kernel<<<296, 256, smem_grul>>>(cell_wih, cell_whh, cell_bih, cell_bhh);
    }

    copy_out_kernel<<<4096, 256>>>((float*)d_out, out_size);
}

// round 4
// speedup vs baseline: 1.0126x; 1.0126x over previous
#include <cuda_runtime.h>
#include <cuda_bf16.h>
#include <math.h>
#include <stdint.h>

#define NPATH 100000
#define NLINK 20000
#define TMAX 8
#define NDEG 48
#define DS 64
#define NITERS 4
#define PADK 72   // bf16 row stride (144B = 36 words) -> conflict-free frag loads
#define PADH 65   // fp32 h_old row stride

// Persistent scratch: uninitialized __device__ globals.
__device__ float g_path_state[NPATH * DS];                 // [P,64]
__device__ float g_link_state[NLINK * DS];                 // [L,64]
__device__ float g_pss[NPATH * (TMAX + 1) * DS];           // [P,9,64]
__device__ float g_agg[NLINK * 4 * DS];                    // [L,256]
__device__ float g_t1[NLINK * 128];
__device__ float g_t2[NLINK * 128];
__device__ float g_pa[NLINK * DS];
// Path-GRU weights: gate-permuted, bf16 hi/lo split, padded rows.
__device__ __nv_bfloat16 g_wih_hi[192 * PADK];
__device__ __nv_bfloat16 g_wih_lo[192 * PADK];
__device__ __nv_bfloat16 g_whh_hi[192 * PADK];
__device__ __nv_bfloat16 g_whh_lo[192 * PADK];
__device__ float g_bih_p[192];
__device__ float g_bhh_p[192];

__device__ __forceinline__ void groupbar(int g) {
    asm volatile("bar.sync %0, 64;" :: "r"(g + 1) : "memory");
}
__device__ __forceinline__ float sigm(float x) { return 1.0f / (1.0f + expf(-x)); }

__device__ __forceinline__ void mma16816(float* c, const uint32_t* a, uint32_t b0, uint32_t b1) {
    asm("mma.sync.aligned.m16n8k16.row.col.f32.bf16.bf16.f32 "
        "{%0,%1,%2,%3}, {%4,%5,%6,%7}, {%8,%9}, {%0,%1,%2,%3};"
        : "+f"(c[0]), "+f"(c[1]), "+f"(c[2]), "+f"(c[3])
        : "r"(a[0]), "r"(a[1]), "r"(a[2]), "r"(a[3]), "r"(b0), "r"(b1));
}

// ---------------------------------------------------------------------------
// Weight prep (once per call): permute rows so chunk c (24 rows) holds the
// complete r/z/n gates for hidden units 8c..8c+7, split fp32 -> bf16 hi+lo.
//   permuted row rp = c*24 + gate*8 + u  <-  original row gate*64 + c*8 + u
// ---------------------------------------------------------------------------
__global__ void prep_weights(const float* __restrict__ wih, const float* __restrict__ whh,
                             const float* __restrict__ bih, const float* __restrict__ bhh) {
    int i = blockIdx.x * blockDim.x + threadIdx.x;
    if (i < 192 * 64) {
        int rp = i >> 6, k = i & 63;
        int c = rp / 24, rem = rp % 24;
        int gate = rem >> 3, u = rem & 7;
        int ro = gate * 64 + c * 8 + u;
        float wi = wih[ro * 64 + k];
        float wh = whh[ro * 64 + k];
        __nv_bfloat16 wihh = __float2bfloat16(wi);
        __nv_bfloat16 wihl = __float2bfloat16(wi - __bfloat162float(wihh));
        __nv_bfloat16 whhh = __float2bfloat16(wh);
        __nv_bfloat16 whhl = __float2bfloat16(wh - __bfloat162float(whhh));
        g_wih_hi[rp * PADK + k] = wihh;
        g_wih_lo[rp * PADK + k] = wihl;
        g_whh_hi[rp * PADK + k] = whhh;
        g_whh_lo[rp * PADK + k] = whhl;
        if (k == 0) { g_bih_p[rp] = bih[ro]; g_bhh_p[rp] = bhh[ro]; }
    }
}

// ---------------------------------------------------------------------------
// One GRU timestep for all paths via bf16 tensor-core MMA (3-term split).
// Block: 256 threads = 8 warps, 128 paths (16 per warp).
// Per warp: gi = x @ Wih'^T + bih', gh = h @ Whh'^T + bhh' (K=64, N=192),
// computed chunk-wise (24 outputs = full r/z/n for 8 units) so the GRU
// pointwise update is thread-local. Masked paths: h frozen, pss[t+1]=0.
// ---------------------------------------------------------------------------
__global__ void __launch_bounds__(256, 1) gru_step_mma(const int* __restrict__ l2p, int t) {
    extern __shared__ char smraw[];
    __nv_bfloat16* sXh   = (__nv_bfloat16*)smraw;        // [128][PADK]
    __nv_bfloat16* sXl   = sXh + 128 * PADK;
    __nv_bfloat16* sHh   = sXl + 128 * PADK;
    __nv_bfloat16* sHl   = sHh + 128 * PADK;
    __nv_bfloat16* sWihH = sHl + 128 * PADK;             // [192][PADK]
    __nv_bfloat16* sWihL = sWihH + 192 * PADK;
    __nv_bfloat16* sWhhH = sWihL + 192 * PADK;
    __nv_bfloat16* sWhhL = sWhhH + 192 * PADK;
    float* sHold = (float*)(sWhhL + 192 * PADK);         // [128][PADH]
    float* sBih  = sHold + 128 * PADH;                   // [192]
    float* sBhh  = sBih + 192;                           // [192]
    int*   sIdx  = (int*)(sBhh + 192);                   // [128]
    int*   sVal  = sIdx + 128;                           // [128]

    int tid = threadIdx.x;
    int pbase = blockIdx.x * 128;

    // stage weights + biases
    for (int i = tid; i < 192 * 64; i += 256) {
        int r = i >> 6, k = i & 63;
        int o = r * PADK + k;
        sWihH[o] = g_wih_hi[o];
        sWihL[o] = g_wih_lo[o];
        sWhhH[o] = g_whh_hi[o];
        sWhhL[o] = g_whh_lo[o];
    }
    if (tid < 192) { sBih[tid] = g_bih_p[tid]; sBhh[tid] = g_bhh_p[tid]; }

    // per-path gather index + valid flag
    if (tid < 128) {
        int p = pbase + tid;
        int idx = -1;
        if (p < NPATH) idx = l2p[p * TMAX + t];
        sIdx[tid] = idx;
        sVal[tid] = (p < NPATH) && (idx != -1);
    }
    __syncthreads();

    // stage x (gathered link state) and h, split fp32 -> bf16 hi/lo
    for (int i = tid; i < 128 * 64; i += 256) {
        int pl = i >> 6, k = i & 63;
        int p = pbase + pl;
        float xv = 0.f, hv = 0.f;
        if (p < NPATH) {
            int idx = sIdx[pl];
            if (idx >= 0) xv = g_link_state[idx * 64 + k];
            hv = g_path_state[p * 64 + k];
        }
        __nv_bfloat16 xh = __float2bfloat16(xv);
        __nv_bfloat16 hh = __float2bfloat16(hv);
        sXh[pl * PADK + k] = xh;
        sXl[pl * PADK + k] = __float2bfloat16(xv - __bfloat162float(xh));
        sHh[pl * PADK + k] = hh;
        sHl[pl * PADK + k] = __float2bfloat16(hv - __bfloat162float(hh));
        sHold[pl * PADH + k] = hv;
    }
    __syncthreads();

    int warp = tid >> 5, lane = tid & 31;
    int gid = lane >> 2, tig = lane & 3;
    int row0 = warp * 16 + gid;
    int row1 = row0 + 8;

    // cache all A fragments (x_hi/x_lo/h_hi/h_lo, 4 k-tiles) in registers
    uint32_t aXh[4][4], aXl[4][4], aHh[4][4], aHl[4][4];
#pragma unroll
    for (int kt = 0; kt < 4; kt++) {
        int kb = kt * 16 + 2 * tig;
        const __nv_bfloat16* r0p = sXh + row0 * PADK + kb;
        const __nv_bfloat16* r1p = sXh + row1 * PADK + kb;
        aXh[kt][0] = *(const uint32_t*)(r0p);
        aXh[kt][1] = *(const uint32_t*)(r1p);
        aXh[kt][2] = *(const uint32_t*)(r0p + 8);
        aXh[kt][3] = *(const uint32_t*)(r1p + 8);
        r0p = sXl + row0 * PADK + kb; r1p = sXl + row1 * PADK + kb;
        aXl[kt][0] = *(const uint32_t*)(r0p);
        aXl[kt][1] = *(const uint32_t*)(r1p);
        aXl[kt][2] = *(const uint32_t*)(r0p + 8);
        aXl[kt][3] = *(const uint32_t*)(r1p + 8);
        r0p = sHh + row0 * PADK + kb; r1p = sHh + row1 * PADK + kb;
        aHh[kt][0] = *(const uint32_t*)(r0p);
        aHh[kt][1] = *(const uint32_t*)(r1p);
        aHh[kt][2] = *(const uint32_t*)(r0p + 8);
        aHh[kt][3] = *(const uint32_t*)(r1p + 8);
        r0p = sHl + row0 * PADK + kb; r1p = sHl + row1 * PADK + kb;
        aHl[kt][0] = *(const uint32_t*)(r0p);
        aHl[kt][1] = *(const uint32_t*)(r1p);
        aHl[kt][2] = *(const uint32_t*)(r0p + 8);
        aHl[kt][3] = *(const uint32_t*)(r1p + 8);
    }

    for (int c = 0; c < 8; c++) {
        float ci[3][4], ch[3][4];
#pragma unroll
        for (int j = 0; j < 3; j++) {
            int nb = c * 24 + j * 8 + 2 * tig;
            float b0 = sBih[nb], b1 = sBih[nb + 1];
            ci[j][0] = b0; ci[j][1] = b1; ci[j][2] = b0; ci[j][3] = b1;
            float d0 = sBhh[nb], d1 = sBhh[nb + 1];
            ch[j][0] = d0; ch[j][1] = d1; ch[j][2] = d0; ch[j][3] = d1;
        }
#pragma unroll
        for (int kt = 0; kt < 4; kt++) {
            int kb = kt * 16 + 2 * tig;
#pragma unroll
            for (int j = 0; j < 3; j++) {
                int nr = (c * 24 + j * 8 + gid) * PADK + kb;
                uint32_t b0, b1;
                b0 = *(const uint32_t*)(sWihH + nr);
                b1 = *(const uint32_t*)(sWihH + nr + 8);
                mma16816(ci[j], aXh[kt], b0, b1);   // x_hi * W_hi
                mma16816(ci[j], aXl[kt], b0, b1);   // x_lo * W_hi
                b0 = *(const uint32_t*)(sWihL + nr);
                b1 = *(const uint32_t*)(sWihL + nr + 8);
                mma16816(ci[j], aXh[kt], b0, b1);   // x_hi * W_lo
                b0 = *(const uint32_t*)(sWhhH + nr);
                b1 = *(const uint32_t*)(sWhhH + nr + 8);
                mma16816(ch[j], aHh[kt], b0, b1);
                mma16816(ch[j], aHl[kt], b0, b1);
                b0 = *(const uint32_t*)(sWhhL + nr);
                b1 = *(const uint32_t*)(sWhhL + nr + 8);
                mma16816(ch[j], aHh[kt], b0, b1);
            }
        }
        // epilogue: thread-local GRU update for units 8c+2tig, 8c+2tig+1
#pragma unroll
        for (int half = 0; half < 2; half++) {
            int lrow = (half == 0) ? row0 : row1;
            int p = pbase + lrow;
            int valid = sVal[lrow];
            int ri = half * 2;
#pragma unroll
            for (int q = 0; q < 2; q++) {
                int u = c * 8 + 2 * tig + q;
                float r = sigm(ci[0][ri + q] + ch[0][ri + q]);
                float z = sigm(ci[1][ri + q] + ch[1][ri + q]);
                float nn = tanhf(ci[2][ri + q] + r * ch[2][ri + q]);
                float hold = sHold[lrow * PADH + u];
                float hn = valid ? ((1.f - z) * nn + z * hold) : hold;
                if (p < NPATH) {
                    g_path_state[p * 64 + u] = hn;
                    g_pss[p * 576 + (t + 1) * 64 + u] = valid ? hn : 0.f;
                    if (t == 0) g_pss[p * 576 + u] = hold;
                }
            }
        }
    }
}

// ---------------------------------------------------------------------------
// Embedding: st[p,d] = relu( relu(x[p]*w1[d]+b1[d]) @ w2^T + b2 )
// ---------------------------------------------------------------------------
template <int TARGET>
__global__ void embed_kernel(const float* __restrict__ x,
                             const float* __restrict__ w1, const float* __restrict__ b1,
                             const float* __restrict__ w2, const float* __restrict__ b2,
                             int n) {
    __shared__ float sW[64 * 64];
    __shared__ float sw1[64], sb1[64], sb2[64];
    __shared__ float sh1[4][64];
    float* st = (TARGET == 0) ? g_path_state : g_link_state;
    int tid = threadIdx.x;
    for (int i = tid; i < 4096; i += 256) {
        int j = i >> 6, k = i & 63;
        sW[k * 64 + j] = w2[i];
    }
    if (tid < 64) { sw1[tid] = w1[tid]; sb1[tid] = b1[tid]; sb2[tid] = b2[tid]; }
    __syncthreads();
    int g = tid >> 6, d = tid & 63;
    for (int base = blockIdx.x * 4; base < n; base += gridDim.x * 4) {
        int p = base + g;
        float h1 = 0.0f;
        if (p < n) {
            float t = x[p];
            h1 = fmaxf(t * sw1[d] + sb1[d], 0.0f);
        }
        sh1[g][d] = h1;
        groupbar(g);
        float acc = sb2[d];
#pragma unroll 8
        for (int k = 0; k < 64; k++) acc += sh1[g][k] * sW[k * 64 + d];
        if (p < n) st[p * 64 + d] = fmaxf(acc, 0.0f);
        groupbar(g);
    }
}

// ---------------------------------------------------------------------------
// Link aggregation: agg[l] = [min | max | sum | mean]
// ---------------------------------------------------------------------------
__global__ void agg_kernel(const int* __restrict__ p2l) {
    __shared__ int s_pi[4][NDEG], s_pos[4][NDEG];
    int tid = threadIdx.x;
    int g = tid >> 6, d = tid & 63;
    for (int base = blockIdx.x * 4; base < NLINK; base += gridDim.x * 4) {
        int l = base + g;
        if (l < NLINK && d < NDEG) {
            s_pi[g][d]  = p2l[(l * NDEG + d) * 2];
            s_pos[g][d] = p2l[(l * NDEG + d) * 2 + 1];
        }
        groupbar(g);
        if (l < NLINK) {
            float vmin = INFINITY, vmax = -INFINITY, vsum = 0.0f;
            int cnt = 0;
            for (int e = 0; e < NDEG; e++) {
                int pi = s_pi[g][e];
                if (pi < 0) continue;
                cnt++;
                float v = g_pss[(pi * 9 + s_pos[g][e]) * 64 + d];
                vmin = fminf(vmin, v);
                vmax = fmaxf(vmax, v);
                vsum += v;
            }
            float mean = vsum / (float)(cnt > 0 ? cnt : 1);
            g_agg[l * 256 + d]        = vmin;
            g_agg[l * 256 + 64 + d]   = vmax;
            g_agg[l * 256 + 128 + d]  = vsum;
            g_agg[l * 256 + 192 + d]  = mean;
        }
        groupbar(g);
    }
}

// ---------------------------------------------------------------------------
// Batched matvec + relu. SRC/DST: 0=g_agg,1=g_t1,2=g_t2,3=g_pa.
// ---------------------------------------------------------------------------
__device__ __forceinline__ float* buf_sel(int s) {
    if (s == 0) return g_agg;
    if (s == 1) return g_t1;
    if (s == 2) return g_t2;
    return g_pa;
}

template <int IN, int OUT, int NL, int SRC, int DST>
__global__ void matvec_relu(const float* __restrict__ W,
                            const float* __restrict__ b, int n) {
    extern __shared__ float sm[];
    float* sWT = sm;
    float* sb  = sWT + IN * OUT;
    float* sin = sb + OUT;
    const float* in = buf_sel(SRC);
    float* out = buf_sel(DST);
    int tid = threadIdx.x;
    for (int i = tid; i < IN * OUT; i += OUT) {
        int j = i / IN, k = i % IN;
        sWT[k * OUT + j] = W[i];
    }
    if (tid < OUT) sb[tid] = b[tid];
    __syncthreads();
    for (int l0 = blockIdx.x * NL; l0 < n; l0 += gridDim.x * NL) {
        for (int i = tid; i < NL * IN; i += OUT) {
            int ll = l0 + i / IN;
            sin[i] = (ll < n) ? in[ll * IN + (i % IN)] : 0.0f;
        }
        __syncthreads();
        float acc[NL];
#pragma unroll
        for (int q = 0; q < NL; q++) acc[q] = sb[tid];
#pragma unroll 4
        for (int k = 0; k < IN; k++) {
            float w = sWT[k * OUT + tid];
#pragma unroll
            for (int q = 0; q < NL; q++) acc[q] += sin[q * IN + k] * w;
        }
#pragma unroll
        for (int q = 0; q < NL; q++) {
            int ll = l0 + q;
            if (ll < n) out[ll * OUT + tid] = fmaxf(acc[q], 0.0f);
        }
        __syncthreads();
    }
}

// ---------------------------------------------------------------------------
// Link GRU cell (single step, in-place on g_link_state). Input = g_pa.
// ---------------------------------------------------------------------------
__global__ void gru_link_kernel(const float* __restrict__ wih, const float* __restrict__ whh,
                                const float* __restrict__ bih, const float* __restrict__ bhh) {
    extern __shared__ float sm[];
    float* sWi = sm;
    float* sWh = sWi + 64 * 192;
    float* sbi = sWh + 64 * 192;
    float* sbh = sbi + 192;
    float* sx  = sbh + 192;
    float* sh  = sx + 4 * 64;
    int tid = threadIdx.x;
    for (int i = tid; i < 192 * 64; i += 256) {
        int j = i / 64, k = i % 64;
        sWi[k * 192 + j] = wih[i];
        sWh[k * 192 + j] = whh[i];
    }
    for (int i = tid; i < 192; i += 256) { sbi[i] = bih[i]; sbh[i] = bhh[i]; }
    __syncthreads();
    int g = tid >> 6, d = tid & 63;
    float* gx = sx + g * 64;
    float* gh = sh + g * 64;
    for (int base = blockIdx.x * 4; base < NLINK; base += gridDim.x * 4) {
        int l = base + g;
        bool e = l < NLINK;
        float hd = 0.0f;
        if (e) {
            gx[d] = g_pa[l * 64 + d];
            hd = g_link_state[l * 64 + d];
            gh[d] = hd;
        } else { gx[d] = 0.0f; gh[d] = 0.0f; }
        groupbar(g);
        float ar = sbi[d], az = sbi[64 + d], an = sbi[128 + d];
        float cr = sbh[d], cz = sbh[64 + d], cn = sbh[128 + d];
#pragma unroll 8
        for (int k = 0; k < 64; k++) {
            float xk = gx[k], hk = gh[k];
            const float* wi = sWi + k * 192;
            const float* wh = sWh + k * 192;
            ar += xk * wi[d];       az += xk * wi[64 + d];  an += xk * wi[128 + d];
            cr += hk * wh[d];       cz += hk * wh[64 + d];  cn += hk * wh[128 + d];
        }
        groupbar(g);
        if (e) {
            float r = sigm(ar + cr);
            float z = sigm(az + cz);
            float nn = tanhf(an + r * cn);
            g_link_state[l * 64 + d] = (1.0f - z) * nn + z * hd;
        }
        groupbar(g);
    }
}

__global__ void copy_out_kernel(float* __restrict__ out, int out_size) {
    const int n1 = NPATH * DS;
    const int n2 = n1 + NLINK * DS;
    for (int i = blockIdx.x * blockDim.x + threadIdx.x; i < out_size;
         i += gridDim.x * blockDim.x) {
        float v = 0.0f;
        if (i < n1) v = g_path_state[i];
        else if (i < n2) v = g_link_state[i - n1];
        out[i] = v;
    }
}

extern "C" void kernel_launch(void* const* d_in, const int* in_sizes, int n_in,
                              void* d_out, int out_size) {
    const float* traffic   = (const float*)d_in[0];
    const float* capacity  = (const float*)d_in[1];
    const int*   l2p       = (const int*)d_in[2];
    const int*   p2l       = (const int*)d_in[3];
    const float* pe_w1 = (const float*)d_in[4];
    const float* pe_b1 = (const float*)d_in[5];
    const float* pe_w2 = (const float*)d_in[6];
    const float* pe_b2 = (const float*)d_in[7];
    const float* le_w1 = (const float*)d_in[8];
    const float* le_b1 = (const float*)d_in[9];
    const float* le_w2 = (const float*)d_in[10];
    const float* le_b2 = (const float*)d_in[11];
    const float* gru_wih = (const float*)d_in[12];
    const float* gru_whh = (const float*)d_in[13];
    const float* gru_bih = (const float*)d_in[14];
    const float* gru_bhh = (const float*)d_in[15];
    const float* cell_wih = (const float*)d_in[16];
    const float* cell_whh = (const float*)d_in[17];
    const float* cell_bih = (const float*)d_in[18];
    const float* cell_bhh = (const float*)d_in[19];
    const float* am_w1 = (const float*)d_in[20];
    const float* am_b1 = (const float*)d_in[21];
    const float* am_w2 = (const float*)d_in[22];
    const float* am_b2 = (const float*)d_in[23];
    const float* am_w3 = (const float*)d_in[24];
    const float* am_b3 = (const float*)d_in[25];

    // dynamic smem sizes
    const size_t smem_mma = (size_t)(4 * 128 * PADK + 4 * 192 * PADK) * 2   // bf16 tiles
                          + (size_t)(128 * PADH + 2 * 192) * 4              // hold + biases
                          + (size_t)(2 * 128) * 4;                          // idx + valid
    const size_t smem_grul = (size_t)(2 * 64 * 192 + 2 * 192 + 2 * 4 * 64) * 4;
    const size_t smem_l1 = (size_t)(256 * 128 + 128 + 4 * 256) * 4;
    const size_t smem_l2 = (size_t)(128 * 128 + 128 + 4 * 128) * 4;
    const size_t smem_l3 = (size_t)(128 * 64 + 64 + 4 * 128) * 4;

    cudaFuncSetAttribute(gru_step_mma, cudaFuncAttributeMaxDynamicSharedMemorySize, (int)smem_mma);
    cudaFuncSetAttribute(gru_link_kernel, cudaFuncAttributeMaxDynamicSharedMemorySize, (int)smem_grul);
    cudaFuncSetAttribute(matvec_relu<256, 128, 4, 0, 1>, cudaFuncAttributeMaxDynamicSharedMemorySize, (int)smem_l1);
    cudaFuncSetAttribute(matvec_relu<128, 128, 4, 1, 2>, cudaFuncAttributeMaxDynamicSharedMemorySize, (int)smem_l2);
    cudaFuncSetAttribute(matvec_relu<128, 64, 4, 2, 3>,  cudaFuncAttributeMaxDynamicSharedMemorySize, (int)smem_l3);

    prep_weights<<<48, 256>>>(gru_wih, gru_whh, gru_bih, gru_bhh);
    embed_kernel<0><<<1024, 256>>>(traffic, pe_w1, pe_b1, pe_w2, pe_b2, NPATH);
    embed_kernel<1><<<512, 256>>>(capacity, le_w1, le_b1, le_w2, le_b2, NLINK);

    const int gru_blocks = (NPATH + 127) / 128;   // 782

    for (int it = 0; it < NITERS; it++) {
        for (int t = 0; t < TMAX; t++) {
            gru_step_mma<<<gru_blocks, 256, smem_mma>>>(l2p, t);
        }
        agg_kernel<<<1024, 256>>>(p2l);
        matvec_relu<256, 128, 4, 0, 1><<<296, 128, smem_l1>>>(am_w1, am_b1, NLINK);
        matvec_relu<128, 128, 4, 1, 2><<<296, 128, smem_l2>>>(am_w2, am_b2, NLINK);
        matvec_relu<128, 64, 4, 2, 3><<<296, 64, smem_l3>>>(am_w3, am_b3, NLINK);
        gru_link_kernel<<<296, 256, smem_grul>>>(cell_wih, cell_whh, cell_bih, cell_bhh);
    }

    copy_out_kernel<<<4096, 256>>>((float*)d_out, out_size);
}

// round 6
// speedup vs baseline: 1.1886x; 1.1738x over previous
#include <cuda_runtime.h>
#include <cuda_bf16.h>
#include <math.h>
#include <stdint.h>

#define NPATH 100000
#define NLINK 20000
#define TMAX 8
#define NDEG 48
#define DS 64
#define NITERS 4
#define PADK 72   // bf16 row stride -> conflict-free frag loads
#define PADH 65   // fp32 h_old row stride

// Persistent scratch: uninitialized __device__ globals.
__device__ float g_path_state[NPATH * DS];
__device__ float g_link_state[NLINK * DS];
__device__ float g_pss[NPATH * (TMAX + 1) * DS];
__device__ float g_agg[NLINK * 4 * DS];
__device__ float g_t1[NLINK * 128];
__device__ float g_t2[NLINK * 128];
__device__ float g_pa[NLINK * DS];
// Path-GRU weights: gate-permuted, bf16 hi/lo split, padded rows.
__device__ __nv_bfloat16 g_wih_hi[192 * PADK];
__device__ __nv_bfloat16 g_wih_lo[192 * PADK];
__device__ __nv_bfloat16 g_whh_hi[192 * PADK];
__device__ __nv_bfloat16 g_whh_lo[192 * PADK];
__device__ float g_bih_p[192];
__device__ float g_bhh_p[192];

__device__ __forceinline__ void groupbar(int g) {
    asm volatile("bar.sync %0, 64;" :: "r"(g + 1) : "memory");
}
__device__ __forceinline__ float sigm(float x) { return 1.0f / (1.0f + expf(-x)); }

__device__ __forceinline__ void mma16816(float* c, const uint32_t* a, uint32_t b0, uint32_t b1) {
    asm("mma.sync.aligned.m16n8k16.row.col.f32.bf16.bf16.f32 "
        "{%0,%1,%2,%3}, {%4,%5,%6,%7}, {%8,%9}, {%0,%1,%2,%3};"
        : "+f"(c[0]), "+f"(c[1]), "+f"(c[2]), "+f"(c[3])
        : "r"(a[0]), "r"(a[1]), "r"(a[2]), "r"(a[3]), "r"(b0), "r"(b1));
}

// ---------------------------------------------------------------------------
// Weight prep: permute rows so chunk c (24 rows) = full r/z/n for units
// 8c..8c+7; split fp32 -> bf16 hi+lo.
// ---------------------------------------------------------------------------
__global__ void prep_weights(const float* __restrict__ wih, const float* __restrict__ whh,
                             const float* __restrict__ bih, const float* __restrict__ bhh) {
    int i = blockIdx.x * blockDim.x + threadIdx.x;
    if (i < 192 * 64) {
        int rp = i >> 6, k = i & 63;
        int c = rp / 24, rem = rp % 24;
        int gate = rem >> 3, u = rem & 7;
        int ro = gate * 64 + c * 8 + u;
        float wi = wih[ro * 64 + k];
        float wh = whh[ro * 64 + k];
        __nv_bfloat16 wihh = __float2bfloat16(wi);
        __nv_bfloat16 wihl = __float2bfloat16(wi - __bfloat162float(wihh));
        __nv_bfloat16 whhh = __float2bfloat16(wh);
        __nv_bfloat16 whhl = __float2bfloat16(wh - __bfloat162float(whhh));
        g_wih_hi[rp * PADK + k] = wihh;
        g_wih_lo[rp * PADK + k] = wihl;
        g_whh_hi[rp * PADK + k] = whhh;
        g_whh_lo[rp * PADK + k] = whhl;
        if (k == 0) { g_bih_p[rp] = bih[ro]; g_bhh_p[rp] = bhh[ro]; }
    }
}

// ---------------------------------------------------------------------------
// FUSED path GRU: one launch per message-passing iteration. Each block owns
// 128 paths for all TMAX steps. Weights staged once; h stays in smem.
// 256 threads = 8 warps; warp w handles path rows [16w,16w+16).
// ---------------------------------------------------------------------------
__global__ void __launch_bounds__(256, 1) gru_path_mma(const int* __restrict__ l2p) {
    extern __shared__ char smraw[];
    __nv_bfloat16* sXh   = (__nv_bfloat16*)smraw;        // [128][PADK]
    __nv_bfloat16* sXl   = sXh + 128 * PADK;
    __nv_bfloat16* sHh   = sXl + 128 * PADK;
    __nv_bfloat16* sHl   = sHh + 128 * PADK;
    __nv_bfloat16* sWihH = sHl + 128 * PADK;             // [192][PADK]
    __nv_bfloat16* sWihL = sWihH + 192 * PADK;
    __nv_bfloat16* sWhhH = sWihL + 192 * PADK;
    __nv_bfloat16* sWhhL = sWhhH + 192 * PADK;
    float* sHold = (float*)(sWhhL + 192 * PADK);         // [128][PADH]
    float* sBih  = sHold + 128 * PADH;                   // [192]
    float* sBhh  = sBih + 192;                           // [192]
    int*   sIdx  = (int*)(sBhh + 192);                   // [128][TMAX]

    int tid = threadIdx.x;
    int pbase = blockIdx.x * 128;

    // stage weights + biases (once)
    for (int i = tid; i < 192 * 64; i += 256) {
        int r = i >> 6, k = i & 63;
        int o = r * PADK + k;
        sWihH[o] = g_wih_hi[o];
        sWihL[o] = g_wih_lo[o];
        sWhhH[o] = g_whh_hi[o];
        sWhhL[o] = g_whh_lo[o];
    }
    if (tid < 192) { sBih[tid] = g_bih_p[tid]; sBhh[tid] = g_bhh_p[tid]; }

    // stage all step indices (coalesced)
    for (int i = tid; i < 128 * TMAX; i += 256) {
        int pl = i / TMAX, tt = i % TMAX;
        int p = pbase + pl;
        sIdx[pl * TMAX + tt] = (p < NPATH) ? l2p[p * TMAX + tt] : -1;
    }

    // stage h0 (split) + write pss[p,0]
    for (int i = tid; i < 128 * 64; i += 256) {
        int pl = i >> 6, k = i & 63;
        int p = pbase + pl;
        float hv = 0.f;
        if (p < NPATH) {
            hv = g_path_state[p * 64 + k];
            g_pss[p * 576 + k] = hv;
        }
        __nv_bfloat16 hh = __float2bfloat16(hv);
        sHh[pl * PADK + k] = hh;
        sHl[pl * PADK + k] = __float2bfloat16(hv - __bfloat162float(hh));
        sHold[pl * PADH + k] = hv;
    }
    __syncthreads();

    int warp = tid >> 5, lane = tid & 31;
    int gid = lane >> 2, tig = lane & 3;
    int row0 = warp * 16 + gid;
    int row1 = row0 + 8;

    for (int t = 0; t < TMAX; t++) {
        // gather x (link states) for this step, split hi/lo
        for (int i = tid; i < 128 * 64; i += 256) {
            int pl = i >> 6, k = i & 63;
            int idx = sIdx[pl * TMAX + t];
            float xv = (idx >= 0) ? g_link_state[idx * 64 + k] : 0.f;
            __nv_bfloat16 xh = __float2bfloat16(xv);
            sXh[pl * PADK + k] = xh;
            sXl[pl * PADK + k] = __float2bfloat16(xv - __bfloat162float(xh));
        }
        __syncthreads();   // gather done (also orders prev-step epilogue h-writes)

        // cache A fragments (x hi/lo, h hi/lo; 4 k-tiles)
        uint32_t aXh[4][4], aXl[4][4], aHh[4][4], aHl[4][4];
#pragma unroll
        for (int kt = 0; kt < 4; kt++) {
            int kb = kt * 16 + 2 * tig;
            const __nv_bfloat16 *r0p, *r1p;
            r0p = sXh + row0 * PADK + kb; r1p = sXh + row1 * PADK + kb;
            aXh[kt][0] = *(const uint32_t*)(r0p);
            aXh[kt][1] = *(const uint32_t*)(r1p);
            aXh[kt][2] = *(const uint32_t*)(r0p + 8);
            aXh[kt][3] = *(const uint32_t*)(r1p + 8);
            r0p = sXl + row0 * PADK + kb; r1p = sXl + row1 * PADK + kb;
            aXl[kt][0] = *(const uint32_t*)(r0p);
            aXl[kt][1] = *(const uint32_t*)(r1p);
            aXl[kt][2] = *(const uint32_t*)(r0p + 8);
            aXl[kt][3] = *(const uint32_t*)(r1p + 8);
            r0p = sHh + row0 * PADK + kb; r1p = sHh + row1 * PADK + kb;
            aHh[kt][0] = *(const uint32_t*)(r0p);
            aHh[kt][1] = *(const uint32_t*)(r1p);
            aHh[kt][2] = *(const uint32_t*)(r0p + 8);
            aHh[kt][3] = *(const uint32_t*)(r1p + 8);
            r0p = sHl + row0 * PADK + kb; r1p = sHl + row1 * PADK + kb;
            aHl[kt][0] = *(const uint32_t*)(r0p);
            aHl[kt][1] = *(const uint32_t*)(r1p);
            aHl[kt][2] = *(const uint32_t*)(r0p + 8);
            aHl[kt][3] = *(const uint32_t*)(r1p + 8);
        }
        __syncthreads();   // all h-frag reads done before epilogue rewrites sH

        for (int c = 0; c < 8; c++) {
            float ci[3][4], ch[3][4];
#pragma unroll
            for (int j = 0; j < 3; j++) {
                int nb = c * 24 + j * 8 + 2 * tig;
                float b0 = sBih[nb], b1 = sBih[nb + 1];
                ci[j][0] = b0; ci[j][1] = b1; ci[j][2] = b0; ci[j][3] = b1;
                float d0 = sBhh[nb], d1 = sBhh[nb + 1];
                ch[j][0] = d0; ch[j][1] = d1; ch[j][2] = d0; ch[j][3] = d1;
            }
#pragma unroll
            for (int kt = 0; kt < 4; kt++) {
                int kb = kt * 16 + 2 * tig;
#pragma unroll
                for (int j = 0; j < 3; j++) {
                    int nr = (c * 24 + j * 8 + gid) * PADK + kb;
                    uint32_t b0, b1;
                    b0 = *(const uint32_t*)(sWihH + nr);
                    b1 = *(const uint32_t*)(sWihH + nr + 8);
                    mma16816(ci[j], aXh[kt], b0, b1);
                    mma16816(ci[j], aXl[kt], b0, b1);
                    b0 = *(const uint32_t*)(sWihL + nr);
                    b1 = *(const uint32_t*)(sWihL + nr + 8);
                    mma16816(ci[j], aXh[kt], b0, b1);
                    b0 = *(const uint32_t*)(sWhhH + nr);
                    b1 = *(const uint32_t*)(sWhhH + nr + 8);
                    mma16816(ch[j], aHh[kt], b0, b1);
                    mma16816(ch[j], aHl[kt], b0, b1);
                    b0 = *(const uint32_t*)(sWhhL + nr);
                    b1 = *(const uint32_t*)(sWhhL + nr + 8);
                    mma16816(ch[j], aHh[kt], b0, b1);
                }
            }
            // epilogue: per-thread GRU update for (row0|row1) x 2 units
#pragma unroll
            for (int half = 0; half < 2; half++) {
                int lrow = (half == 0) ? row0 : row1;
                int p = pbase + lrow;
                int valid = sIdx[lrow * TMAX + t] >= 0;
                int ri = half * 2;
#pragma unroll
                for (int q = 0; q < 2; q++) {
                    int u = c * 8 + 2 * tig + q;
                    float r = sigm(ci[0][ri + q] + ch[0][ri + q]);
                    float z = sigm(ci[1][ri + q] + ch[1][ri + q]);
                    float nn = tanhf(ci[2][ri + q] + r * ch[2][ri + q]);
                    float hold = sHold[lrow * PADH + u];
                    float hn = valid ? ((1.f - z) * nn + z * hold) : hold;
                    sHold[lrow * PADH + u] = hn;
                    __nv_bfloat16 hh = __float2bfloat16(hn);
                    sHh[lrow * PADK + u] = hh;
                    sHl[lrow * PADK + u] = __float2bfloat16(hn - __bfloat162float(hh));
                    if (p < NPATH)
                        g_pss[p * 576 + (t + 1) * 64 + u] = valid ? hn : 0.f;
                }
            }
        }
        __syncthreads();   // epilogue h-writes complete before next gather/frags
    }

    // final path_state writeback (coalesced)
    for (int i = tid; i < 128 * 64; i += 256) {
        int pl = i >> 6, k = i & 63;
        int p = pbase + pl;
        if (p < NPATH) g_path_state[p * 64 + k] = sHold[pl * PADH + k];
    }
}

// ---------------------------------------------------------------------------
// Embedding
// ---------------------------------------------------------------------------
template <int TARGET>
__global__ void embed_kernel(const float* __restrict__ x,
                             const float* __restrict__ w1, const float* __restrict__ b1,
                             const float* __restrict__ w2, const float* __restrict__ b2,
                             int n) {
    __shared__ float sW[64 * 64];
    __shared__ float sw1[64], sb1[64], sb2[64];
    __shared__ float sh1[4][64];
    float* st = (TARGET == 0) ? g_path_state : g_link_state;
    int tid = threadIdx.x;
    for (int i = tid; i < 4096; i += 256) {
        int j = i >> 6, k = i & 63;
        sW[k * 64 + j] = w2[i];
    }
    if (tid < 64) { sw1[tid] = w1[tid]; sb1[tid] = b1[tid]; sb2[tid] = b2[tid]; }
    __syncthreads();
    int g = tid >> 6, d = tid & 63;
    for (int base = blockIdx.x * 4; base < n; base += gridDim.x * 4) {
        int p = base + g;
        float h1 = 0.0f;
        if (p < n) {
            float t = x[p];
            h1 = fmaxf(t * sw1[d] + sb1[d], 0.0f);
        }
        sh1[g][d] = h1;
        groupbar(g);
        float acc = sb2[d];
#pragma unroll 8
        for (int k = 0; k < 64; k++) acc += sh1[g][k] * sW[k * 64 + d];
        if (p < n) st[p * 64 + d] = fmaxf(acc, 0.0f);
        groupbar(g);
    }
}

// ---------------------------------------------------------------------------
// Link aggregation
// ---------------------------------------------------------------------------
__global__ void agg_kernel(const int* __restrict__ p2l) {
    __shared__ int s_pi[4][NDEG], s_pos[4][NDEG];
    int tid = threadIdx.x;
    int g = tid >> 6, d = tid & 63;
    for (int base = blockIdx.x * 4; base < NLINK; base += gridDim.x * 4) {
        int l = base + g;
        if (l < NLINK && d < NDEG) {
            s_pi[g][d]  = p2l[(l * NDEG + d) * 2];
            s_pos[g][d] = p2l[(l * NDEG + d) * 2 + 1];
        }
        groupbar(g);
        if (l < NLINK) {
            float vmin = INFINITY, vmax = -INFINITY, vsum = 0.0f;
            int cnt = 0;
            for (int e = 0; e < NDEG; e++) {
                int pi = s_pi[g][e];
                if (pi < 0) continue;
                cnt++;
                float v = g_pss[(pi * 9 + s_pos[g][e]) * 64 + d];
                vmin = fminf(vmin, v);
                vmax = fmaxf(vmax, v);
                vsum += v;
            }
            float mean = vsum / (float)(cnt > 0 ? cnt : 1);
            g_agg[l * 256 + d]        = vmin;
            g_agg[l * 256 + 64 + d]   = vmax;
            g_agg[l * 256 + 128 + d]  = vsum;
            g_agg[l * 256 + 192 + d]  = mean;
        }
        groupbar(g);
    }
}

// ---------------------------------------------------------------------------
// Batched matvec + relu. SRC/DST: 0=g_agg,1=g_t1,2=g_t2,3=g_pa.
// ---------------------------------------------------------------------------
__device__ __forceinline__ float* buf_sel(int s) {
    if (s == 0) return g_agg;
    if (s == 1) return g_t1;
    if (s == 2) return g_t2;
    return g_pa;
}

template <int IN, int OUT, int NL, int SRC, int DST>
__global__ void matvec_relu(const float* __restrict__ W,
                            const float* __restrict__ b, int n) {
    extern __shared__ float sm[];
    float* sWT = sm;
    float* sb  = sWT + IN * OUT;
    float* sin = sb + OUT;
    const float* in = buf_sel(SRC);
    float* out = buf_sel(DST);
    int tid = threadIdx.x;
    for (int i = tid; i < IN * OUT; i += OUT) {
        int j = i / IN, k = i % IN;
        sWT[k * OUT + j] = W[i];
    }
    if (tid < OUT) sb[tid] = b[tid];
    __syncthreads();
    for (int l0 = blockIdx.x * NL; l0 < n; l0 += gridDim.x * NL) {
        for (int i = tid; i < NL * IN; i += OUT) {
            int ll = l0 + i / IN;
            sin[i] = (ll < n) ? in[ll * IN + (i % IN)] : 0.0f;
        }
        __syncthreads();
        float acc[NL];
#pragma unroll
        for (int q = 0; q < NL; q++) acc[q] = sb[tid];
#pragma unroll 4
        for (int k = 0; k < IN; k++) {
            float w = sWT[k * OUT + tid];
#pragma unroll
            for (int q = 0; q < NL; q++) acc[q] += sin[q * IN + k] * w;
        }
#pragma unroll
        for (int q = 0; q < NL; q++) {
            int ll = l0 + q;
            if (ll < n) out[ll * OUT + tid] = fmaxf(acc[q], 0.0f);
        }
        __syncthreads();
    }
}

// ---------------------------------------------------------------------------
// Link GRU cell
// ---------------------------------------------------------------------------
__global__ void gru_link_kernel(const float* __restrict__ wih, const float* __restrict__ whh,
                                const float* __restrict__ bih, const float* __restrict__ bhh) {
    extern __shared__ float sm[];
    float* sWi = sm;
    float* sWh = sWi + 64 * 192;
    float* sbi = sWh + 64 * 192;
    float* sbh = sbi + 192;
    float* sx  = sbh + 192;
    float* sh  = sx + 4 * 64;
    int tid = threadIdx.x;
    for (int i = tid; i < 192 * 64; i += 256) {
        int j = i / 64, k = i % 64;
        sWi[k * 192 + j] = wih[i];
        sWh[k * 192 + j] = whh[i];
    }
    for (int i = tid; i < 192; i += 256) { sbi[i] = bih[i]; sbh[i] = bhh[i]; }
    __syncthreads();
    int g = tid >> 6, d = tid & 63;
    float* gx = sx + g * 64;
    float* gh = sh + g * 64;
    for (int base = blockIdx.x * 4; base < NLINK; base += gridDim.x * 4) {
        int l = base + g;
        bool e = l < NLINK;
        float hd = 0.0f;
        if (e) {
            gx[d] = g_pa[l * 64 + d];
            hd = g_link_state[l * 64 + d];
            gh[d] = hd;
        } else { gx[d] = 0.0f; gh[d] = 0.0f; }
        groupbar(g);
        float ar = sbi[d], az = sbi[64 + d], an = sbi[128 + d];
        float cr = sbh[d], cz = sbh[64 + d], cn = sbh[128 + d];
#pragma unroll 8
        for (int k = 0; k < 64; k++) {
            float xk = gx[k], hk = gh[k];
            const float* wi = sWi + k * 192;
            const float* wh = sWh + k * 192;
            ar += xk * wi[d];       az += xk * wi[64 + d];  an += xk * wi[128 + d];
            cr += hk * wh[d];       cz += hk * wh[64 + d];  cn += hk * wh[128 + d];
        }
        groupbar(g);
        if (e) {
            float r = sigm(ar + cr);
            float z = sigm(az + cz);
            float nn = tanhf(an + r * cn);
            g_link_state[l * 64 + d] = (1.0f - z) * nn + z * hd;
        }
        groupbar(g);
    }
}

__global__ void copy_out_kernel(float* __restrict__ out, int out_size) {
    const int n1 = NPATH * DS;
    const int n2 = n1 + NLINK * DS;
    for (int i = blockIdx.x * blockDim.x + threadIdx.x; i < out_size;
         i += gridDim.x * blockDim.x) {
        float v = 0.0f;
        if (i < n1) v = g_path_state[i];
        else if (i < n2) v = g_link_state[i - n1];
        out[i] = v;
    }
}

extern "C" void kernel_launch(void* const* d_in, const int* in_sizes, int n_in,
                              void* d_out, int out_size) {
    const float* traffic   = (const float*)d_in[0];
    const float* capacity  = (const float*)d_in[1];
    const int*   l2p       = (const int*)d_in[2];
    const int*   p2l       = (const int*)d_in[3];
    const float* pe_w1 = (const float*)d_in[4];
    const float* pe_b1 = (const float*)d_in[5];
    const float* pe_w2 = (const float*)d_in[6];
    const float* pe_b2 = (const float*)d_in[7];
    const float* le_w1 = (const float*)d_in[8];
    const float* le_b1 = (const float*)d_in[9];
    const float* le_w2 = (const float*)d_in[10];
    const float* le_b2 = (const float*)d_in[11];
    const float* gru_wih = (const float*)d_in[12];
    const float* gru_whh = (const float*)d_in[13];
    const float* gru_bih = (const float*)d_in[14];
    const float* gru_bhh = (const float*)d_in[15];
    const float* cell_wih = (const float*)d_in[16];
    const float* cell_whh = (const float*)d_in[17];
    const float* cell_bih = (const float*)d_in[18];
    const float* cell_bhh = (const float*)d_in[19];
    const float* am_w1 = (const float*)d_in[20];
    const float* am_b1 = (const float*)d_in[21];
    const float* am_w2 = (const float*)d_in[22];
    const float* am_b2 = (const float*)d_in[23];
    const float* am_w3 = (const float*)d_in[24];
    const float* am_b3 = (const float*)d_in[25];

    const size_t smem_mma = (size_t)(4 * 128 * PADK + 4 * 192 * PADK) * 2   // bf16 tiles
                          + (size_t)(128 * PADH + 2 * 192) * 4              // hold + biases
                          + (size_t)(128 * TMAX) * 4;                       // idx
    const size_t smem_grul = (size_t)(2 * 64 * 192 + 2 * 192 + 2 * 4 * 64) * 4;
    const size_t smem_l1 = (size_t)(256 * 128 + 128 + 4 * 256) * 4;
    const size_t smem_l2 = (size_t)(128 * 128 + 128 + 4 * 128) * 4;
    const size_t smem_l3 = (size_t)(128 * 64 + 64 + 4 * 128) * 4;

    cudaFuncSetAttribute(gru_path_mma, cudaFuncAttributeMaxDynamicSharedMemorySize, (int)smem_mma);
    cudaFuncSetAttribute(gru_link_kernel, cudaFuncAttributeMaxDynamicSharedMemorySize, (int)smem_grul);
    cudaFuncSetAttribute(matvec_relu<256, 128, 4, 0, 1>, cudaFuncAttributeMaxDynamicSharedMemorySize, (int)smem_l1);
    cudaFuncSetAttribute(matvec_relu<128, 128, 4, 1, 2>, cudaFuncAttributeMaxDynamicSharedMemorySize, (int)smem_l2);
    cudaFuncSetAttribute(matvec_relu<128, 64, 4, 2, 3>,  cudaFuncAttributeMaxDynamicSharedMemorySize, (int)smem_l3);

    prep_weights<<<48, 256>>>(gru_wih, gru_whh, gru_bih, gru_bhh);
    embed_kernel<0><<<1024, 256>>>(traffic, pe_w1, pe_b1, pe_w2, pe_b2, NPATH);
    embed_kernel<1><<<512, 256>>>(capacity, le_w1, le_b1, le_w2, le_b2, NLINK);

    const int gru_blocks = (NPATH + 127) / 128;   // 782

    for (int it = 0; it < NITERS; it++) {
        gru_path_mma<<<gru_blocks, 256, smem_mma>>>(l2p);
        agg_kernel<<<1024, 256>>>(p2l);
        matvec_relu<256, 128, 4, 0, 1><<<296, 128, smem_l1>>>(am_w1, am_b1, NLINK);
        matvec_relu<128, 128, 4, 1, 2><<<296, 128, smem_l2>>>(am_w2, am_b2, NLINK);
        matvec_relu<128, 64, 4, 2, 3><<<296, 64, smem_l3>>>(am_w3, am_b3, NLINK);
        gru_link_kernel<<<296, 256, smem_grul>>>(cell_wih, cell_whh, cell_bih, cell_bhh);
    }

    copy_out_kernel<<<4096, 256>>>((float*)d_out, out_size);
}

// round 7
// speedup vs baseline: 1.4574x; 1.2262x over previous
#include <cuda_runtime.h>
#include <cuda_bf16.h>
#include <math.h>
#include <stdint.h>

#define NPATH 100000
#define NLINK 20000
#define TMAX 8
#define NDEG 48
#define DS 64
#define NITERS 4
#define PADK 72   // bf16 row stride -> conflict-free frag loads
#define PADH 65   // fp32 h_old row stride

// Persistent scratch: uninitialized __device__ globals.
__device__ float g_path_state[NPATH * DS];
__device__ float g_link_state[NLINK * DS];
__device__ float g_pss[NPATH * (TMAX + 1) * DS];
__device__ float g_agg[NLINK * 4 * DS];
__device__ float g_t1[NLINK * 128];
__device__ float g_t2[NLINK * 128];
__device__ float g_pa[NLINK * DS];
// Path-GRU weights: gate-permuted, bf16 hi/lo split, padded rows.
__device__ __nv_bfloat16 g_wih_hi[192 * PADK];
__device__ __nv_bfloat16 g_wih_lo[192 * PADK];
__device__ __nv_bfloat16 g_whh_hi[192 * PADK];
__device__ __nv_bfloat16 g_whh_lo[192 * PADK];
__device__ float g_bih_p[192];
__device__ float g_bhh_p[192];

__device__ __forceinline__ void groupbar(int g) {
    asm volatile("bar.sync %0, 64;" :: "r"(g + 1) : "memory");
}
__device__ __forceinline__ float sigm(float x) { return 1.0f / (1.0f + expf(-x)); }

__device__ __forceinline__ void mma16816(float* c, const uint32_t* a, uint32_t b0, uint32_t b1) {
    asm("mma.sync.aligned.m16n8k16.row.col.f32.bf16.bf16.f32 "
        "{%0,%1,%2,%3}, {%4,%5,%6,%7}, {%8,%9}, {%0,%1,%2,%3};"
        : "+f"(c[0]), "+f"(c[1]), "+f"(c[2]), "+f"(c[3])
        : "r"(a[0]), "r"(a[1]), "r"(a[2]), "r"(a[3]), "r"(b0), "r"(b1));
}

// ---------------------------------------------------------------------------
// Weight prep: permute rows so chunk c (24 rows) = full r/z/n for units
// 8c..8c+7; split fp32 -> bf16 hi+lo.
// ---------------------------------------------------------------------------
__global__ void prep_weights(const float* __restrict__ wih, const float* __restrict__ whh,
                             const float* __restrict__ bih, const float* __restrict__ bhh) {
    int i = blockIdx.x * blockDim.x + threadIdx.x;
    if (i < 192 * 64) {
        int rp = i >> 6, k = i & 63;
        int c = rp / 24, rem = rp % 24;
        int gate = rem >> 3, u = rem & 7;
        int ro = gate * 64 + c * 8 + u;
        float wi = wih[ro * 64 + k];
        float wh = whh[ro * 64 + k];
        __nv_bfloat16 wihh = __float2bfloat16(wi);
        __nv_bfloat16 wihl = __float2bfloat16(wi - __bfloat162float(wihh));
        __nv_bfloat16 whhh = __float2bfloat16(wh);
        __nv_bfloat16 whhl = __float2bfloat16(wh - __bfloat162float(whhh));
        g_wih_hi[rp * PADK + k] = wihh;
        g_wih_lo[rp * PADK + k] = wihl;
        g_whh_hi[rp * PADK + k] = whhh;
        g_whh_lo[rp * PADK + k] = whhl;
        if (k == 0) { g_bih_p[rp] = bih[ro]; g_bhh_p[rp] = bhh[ro]; }
    }
}

// ---------------------------------------------------------------------------
// FUSED path GRU, N-split: 512 threads = 16 warps. Warp w owns M-rows
// [16*(w&7), 16*(w&7)+16) and N-chunk half (w>>3): chunks [4*nh, 4*nh+4).
// Each block owns 128 paths for all TMAX steps; weights staged once; h in smem.
// ---------------------------------------------------------------------------
__global__ void __launch_bounds__(512, 1) gru_path_mma(const int* __restrict__ l2p) {
    extern __shared__ char smraw[];
    __nv_bfloat16* sXh   = (__nv_bfloat16*)smraw;        // [128][PADK]
    __nv_bfloat16* sXl   = sXh + 128 * PADK;
    __nv_bfloat16* sHh   = sXl + 128 * PADK;
    __nv_bfloat16* sHl   = sHh + 128 * PADK;
    __nv_bfloat16* sWihH = sHl + 128 * PADK;             // [192][PADK]
    __nv_bfloat16* sWihL = sWihH + 192 * PADK;
    __nv_bfloat16* sWhhH = sWihL + 192 * PADK;
    __nv_bfloat16* sWhhL = sWhhH + 192 * PADK;
    float* sHold = (float*)(sWhhL + 192 * PADK);         // [128][PADH]
    float* sBih  = sHold + 128 * PADH;                   // [192]
    float* sBhh  = sBih + 192;                           // [192]
    int*   sIdx  = (int*)(sBhh + 192);                   // [128][TMAX]

    int tid = threadIdx.x;
    int pbase = blockIdx.x * 128;

    // stage weights + biases (once)
    for (int i = tid; i < 192 * 64; i += 512) {
        int r = i >> 6, k = i & 63;
        int o = r * PADK + k;
        sWihH[o] = g_wih_hi[o];
        sWihL[o] = g_wih_lo[o];
        sWhhH[o] = g_whh_hi[o];
        sWhhL[o] = g_whh_lo[o];
    }
    if (tid < 192) { sBih[tid] = g_bih_p[tid]; sBhh[tid] = g_bhh_p[tid]; }

    // stage all step indices (coalesced)
    for (int i = tid; i < 128 * TMAX; i += 512) {
        int pl = i / TMAX, tt = i % TMAX;
        int p = pbase + pl;
        sIdx[pl * TMAX + tt] = (p < NPATH) ? l2p[p * TMAX + tt] : -1;
    }

    // stage h0 (split) + write pss[p,0]
    for (int i = tid; i < 128 * 64; i += 512) {
        int pl = i >> 6, k = i & 63;
        int p = pbase + pl;
        float hv = 0.f;
        if (p < NPATH) {
            hv = g_path_state[p * 64 + k];
            g_pss[p * 576 + k] = hv;
        }
        __nv_bfloat16 hh = __float2bfloat16(hv);
        sHh[pl * PADK + k] = hh;
        sHl[pl * PADK + k] = __float2bfloat16(hv - __bfloat162float(hh));
        sHold[pl * PADH + k] = hv;
    }
    __syncthreads();

    int warp = tid >> 5, lane = tid & 31;
    int mw = warp & 7, nh = warp >> 3;
    int gid = lane >> 2, tig = lane & 3;
    int row0 = mw * 16 + gid;
    int row1 = row0 + 8;

    for (int t = 0; t < TMAX; t++) {
        // gather x (link states) for this step, split hi/lo
        for (int i = tid; i < 128 * 64; i += 512) {
            int pl = i >> 6, k = i & 63;
            int idx = sIdx[pl * TMAX + t];
            float xv = (idx >= 0) ? g_link_state[idx * 64 + k] : 0.f;
            __nv_bfloat16 xh = __float2bfloat16(xv);
            sXh[pl * PADK + k] = xh;
            sXl[pl * PADK + k] = __float2bfloat16(xv - __bfloat162float(xh));
        }
        __syncthreads();   // gather done (also orders prev-step epilogue h-writes)

        // cache A fragments (x hi/lo, h hi/lo; 4 k-tiles)
        uint32_t aXh[4][4], aXl[4][4], aHh[4][4], aHl[4][4];
#pragma unroll
        for (int kt = 0; kt < 4; kt++) {
            int kb = kt * 16 + 2 * tig;
            const __nv_bfloat16 *r0p, *r1p;
            r0p = sXh + row0 * PADK + kb; r1p = sXh + row1 * PADK + kb;
            aXh[kt][0] = *(const uint32_t*)(r0p);
            aXh[kt][1] = *(const uint32_t*)(r1p);
            aXh[kt][2] = *(const uint32_t*)(r0p + 8);
            aXh[kt][3] = *(const uint32_t*)(r1p + 8);
            r0p = sXl + row0 * PADK + kb; r1p = sXl + row1 * PADK + kb;
            aXl[kt][0] = *(const uint32_t*)(r0p);
            aXl[kt][1] = *(const uint32_t*)(r1p);
            aXl[kt][2] = *(const uint32_t*)(r0p + 8);
            aXl[kt][3] = *(const uint32_t*)(r1p + 8);
            r0p = sHh + row0 * PADK + kb; r1p = sHh + row1 * PADK + kb;
            aHh[kt][0] = *(const uint32_t*)(r0p);
            aHh[kt][1] = *(const uint32_t*)(r1p);
            aHh[kt][2] = *(const uint32_t*)(r0p + 8);
            aHh[kt][3] = *(const uint32_t*)(r1p + 8);
            r0p = sHl + row0 * PADK + kb; r1p = sHl + row1 * PADK + kb;
            aHl[kt][0] = *(const uint32_t*)(r0p);
            aHl[kt][1] = *(const uint32_t*)(r1p);
            aHl[kt][2] = *(const uint32_t*)(r0p + 8);
            aHl[kt][3] = *(const uint32_t*)(r1p + 8);
        }
        __syncthreads();   // all h-frag reads done before epilogue rewrites sH

        for (int c = nh * 4; c < nh * 4 + 4; c++) {
            float ci[3][4], ch[3][4];
#pragma unroll
            for (int j = 0; j < 3; j++) {
                int nb = c * 24 + j * 8 + 2 * tig;
                float b0 = sBih[nb], b1 = sBih[nb + 1];
                ci[j][0] = b0; ci[j][1] = b1; ci[j][2] = b0; ci[j][3] = b1;
                float d0 = sBhh[nb], d1 = sBhh[nb + 1];
                ch[j][0] = d0; ch[j][1] = d1; ch[j][2] = d0; ch[j][3] = d1;
            }
#pragma unroll
            for (int kt = 0; kt < 4; kt++) {
                int kb = kt * 16 + 2 * tig;
#pragma unroll
                for (int j = 0; j < 3; j++) {
                    int nr = (c * 24 + j * 8 + gid) * PADK + kb;
                    uint32_t b0, b1;
                    b0 = *(const uint32_t*)(sWihH + nr);
                    b1 = *(const uint32_t*)(sWihH + nr + 8);
                    mma16816(ci[j], aXh[kt], b0, b1);
                    mma16816(ci[j], aXl[kt], b0, b1);
                    b0 = *(const uint32_t*)(sWihL + nr);
                    b1 = *(const uint32_t*)(sWihL + nr + 8);
                    mma16816(ci[j], aXh[kt], b0, b1);
                    b0 = *(const uint32_t*)(sWhhH + nr);
                    b1 = *(const uint32_t*)(sWhhH + nr + 8);
                    mma16816(ch[j], aHh[kt], b0, b1);
                    mma16816(ch[j], aHl[kt], b0, b1);
                    b0 = *(const uint32_t*)(sWhhL + nr);
                    b1 = *(const uint32_t*)(sWhhL + nr + 8);
                    mma16816(ch[j], aHh[kt], b0, b1);
                }
            }
            // epilogue: per-thread GRU update for (row0|row1) x 2 units
#pragma unroll
            for (int half = 0; half < 2; half++) {
                int lrow = (half == 0) ? row0 : row1;
                int p = pbase + lrow;
                int valid = sIdx[lrow * TMAX + t] >= 0;
                int ri = half * 2;
#pragma unroll
                for (int q = 0; q < 2; q++) {
                    int u = c * 8 + 2 * tig + q;
                    float r = sigm(ci[0][ri + q] + ch[0][ri + q]);
                    float z = sigm(ci[1][ri + q] + ch[1][ri + q]);
                    float nn = tanhf(ci[2][ri + q] + r * ch[2][ri + q]);
                    float hold = sHold[lrow * PADH + u];
                    float hn = valid ? ((1.f - z) * nn + z * hold) : hold;
                    sHold[lrow * PADH + u] = hn;
                    __nv_bfloat16 hh = __float2bfloat16(hn);
                    sHh[lrow * PADK + u] = hh;
                    sHl[lrow * PADK + u] = __float2bfloat16(hn - __bfloat162float(hh));
                    if (p < NPATH)
                        g_pss[p * 576 + (t + 1) * 64 + u] = valid ? hn : 0.f;
                }
            }
        }
        __syncthreads();   // epilogue h-writes complete before next gather/frags
    }

    // final path_state writeback (coalesced)
    for (int i = tid; i < 128 * 64; i += 512) {
        int pl = i >> 6, k = i & 63;
        int p = pbase + pl;
        if (p < NPATH) g_path_state[p * 64 + k] = sHold[pl * PADH + k];
    }
}

// ---------------------------------------------------------------------------
// Embedding
// ---------------------------------------------------------------------------
template <int TARGET>
__global__ void embed_kernel(const float* __restrict__ x,
                             const float* __restrict__ w1, const float* __restrict__ b1,
                             const float* __restrict__ w2, const float* __restrict__ b2,
                             int n) {
    __shared__ float sW[64 * 64];
    __shared__ float sw1[64], sb1[64], sb2[64];
    __shared__ float sh1[4][64];
    float* st = (TARGET == 0) ? g_path_state : g_link_state;
    int tid = threadIdx.x;
    for (int i = tid; i < 4096; i += 256) {
        int j = i >> 6, k = i & 63;
        sW[k * 64 + j] = w2[i];
    }
    if (tid < 64) { sw1[tid] = w1[tid]; sb1[tid] = b1[tid]; sb2[tid] = b2[tid]; }
    __syncthreads();
    int g = tid >> 6, d = tid & 63;
    for (int base = blockIdx.x * 4; base < n; base += gridDim.x * 4) {
        int p = base + g;
        float h1 = 0.0f;
        if (p < n) {
            float t = x[p];
            h1 = fmaxf(t * sw1[d] + sb1[d], 0.0f);
        }
        sh1[g][d] = h1;
        groupbar(g);
        float acc = sb2[d];
#pragma unroll 8
        for (int k = 0; k < 64; k++) acc += sh1[g][k] * sW[k * 64 + d];
        if (p < n) st[p * 64 + d] = fmaxf(acc, 0.0f);
        groupbar(g);
    }
}

// ---------------------------------------------------------------------------
// Link aggregation
// ---------------------------------------------------------------------------
__global__ void agg_kernel(const int* __restrict__ p2l) {
    __shared__ int s_pi[4][NDEG], s_pos[4][NDEG];
    int tid = threadIdx.x;
    int g = tid >> 6, d = tid & 63;
    for (int base = blockIdx.x * 4; base < NLINK; base += gridDim.x * 4) {
        int l = base + g;
        if (l < NLINK && d < NDEG) {
            s_pi[g][d]  = p2l[(l * NDEG + d) * 2];
            s_pos[g][d] = p2l[(l * NDEG + d) * 2 + 1];
        }
        groupbar(g);
        if (l < NLINK) {
            float vmin = INFINITY, vmax = -INFINITY, vsum = 0.0f;
            int cnt = 0;
            for (int e = 0; e < NDEG; e++) {
                int pi = s_pi[g][e];
                if (pi < 0) continue;
                cnt++;
                float v = g_pss[(pi * 9 + s_pos[g][e]) * 64 + d];
                vmin = fminf(vmin, v);
                vmax = fmaxf(vmax, v);
                vsum += v;
            }
            float mean = vsum / (float)(cnt > 0 ? cnt : 1);
            g_agg[l * 256 + d]        = vmin;
            g_agg[l * 256 + 64 + d]   = vmax;
            g_agg[l * 256 + 128 + d]  = vsum;
            g_agg[l * 256 + 192 + d]  = mean;
        }
        groupbar(g);
    }
}

// ---------------------------------------------------------------------------
// Batched matvec + relu. SRC/DST: 0=g_agg,1=g_t1,2=g_t2,3=g_pa.
// ---------------------------------------------------------------------------
__device__ __forceinline__ float* buf_sel(int s) {
    if (s == 0) return g_agg;
    if (s == 1) return g_t1;
    if (s == 2) return g_t2;
    return g_pa;
}

template <int IN, int OUT, int NL, int SRC, int DST>
__global__ void matvec_relu(const float* __restrict__ W,
                            const float* __restrict__ b, int n) {
    extern __shared__ float sm[];
    float* sWT = sm;
    float* sb  = sWT + IN * OUT;
    float* sin = sb + OUT;
    const float* in = buf_sel(SRC);
    float* out = buf_sel(DST);
    int tid = threadIdx.x;
    for (int i = tid; i < IN * OUT; i += OUT) {
        int j = i / IN, k = i % IN;
        sWT[k * OUT + j] = W[i];
    }
    if (tid < OUT) sb[tid] = b[tid];
    __syncthreads();
    for (int l0 = blockIdx.x * NL; l0 < n; l0 += gridDim.x * NL) {
        for (int i = tid; i < NL * IN; i += OUT) {
            int ll = l0 + i / IN;
            sin[i] = (ll < n) ? in[ll * IN + (i % IN)] : 0.0f;
        }
        __syncthreads();
        float acc[NL];
#pragma unroll
        for (int q = 0; q < NL; q++) acc[q] = sb[tid];
#pragma unroll 4
        for (int k = 0; k < IN; k++) {
            float w = sWT[k * OUT + tid];
#pragma unroll
            for (int q = 0; q < NL; q++) acc[q] += sin[q * IN + k] * w;
        }
#pragma unroll
        for (int q = 0; q < NL; q++) {
            int ll = l0 + q;
            if (ll < n) out[ll * OUT + tid] = fmaxf(acc[q], 0.0f);
        }
        __syncthreads();
    }
}

// ---------------------------------------------------------------------------
// Link GRU cell
// ---------------------------------------------------------------------------
__global__ void gru_link_kernel(const float* __restrict__ wih, const float* __restrict__ whh,
                                const float* __restrict__ bih, const float* __restrict__ bhh) {
    extern __shared__ float sm[];
    float* sWi = sm;
    float* sWh = sWi + 64 * 192;
    float* sbi = sWh + 64 * 192;
    float* sbh = sbi + 192;
    float* sx  = sbh + 192;
    float* sh  = sx + 4 * 64;
    int tid = threadIdx.x;
    for (int i = tid; i < 192 * 64; i += 256) {
        int j = i / 64, k = i % 64;
        sWi[k * 192 + j] = wih[i];
        sWh[k * 192 + j] = whh[i];
    }
    for (int i = tid; i < 192; i += 256) { sbi[i] = bih[i]; sbh[i] = bhh[i]; }
    __syncthreads();
    int g = tid >> 6, d = tid & 63;
    float* gx = sx + g * 64;
    float* gh = sh + g * 64;
    for (int base = blockIdx.x * 4; base < NLINK; base += gridDim.x * 4) {
        int l = base + g;
        bool e = l < NLINK;
        float hd = 0.0f;
        if (e) {
            gx[d] = g_pa[l * 64 + d];
            hd = g_link_state[l * 64 + d];
            gh[d] = hd;
        } else { gx[d] = 0.0f; gh[d] = 0.0f; }
        groupbar(g);
        float ar = sbi[d], az = sbi[64 + d], an = sbi[128 + d];
        float cr = sbh[d], cz = sbh[64 + d], cn = sbh[128 + d];
#pragma unroll 8
        for (int k = 0; k < 64; k++) {
            float xk = gx[k], hk = gh[k];
            const float* wi = sWi + k * 192;
            const float* wh = sWh + k * 192;
            ar += xk * wi[d];       az += xk * wi[64 + d];  an += xk * wi[128 + d];
            cr += hk * wh[d];       cz += hk * wh[64 + d];  cn += hk * wh[128 + d];
        }
        groupbar(g);
        if (e) {
            float r = sigm(ar + cr);
            float z = sigm(az + cz);
            float nn = tanhf(an + r * cn);
            g_link_state[l * 64 + d] = (1.0f - z) * nn + z * hd;
        }
        groupbar(g);
    }
}

__global__ void copy_out_kernel(float* __restrict__ out, int out_size) {
    const int n1 = NPATH * DS;
    const int n2 = n1 + NLINK * DS;
    for (int i = blockIdx.x * blockDim.x + threadIdx.x; i < out_size;
         i += gridDim.x * blockDim.x) {
        float v = 0.0f;
        if (i < n1) v = g_path_state[i];
        else if (i < n2) v = g_link_state[i - n1];
        out[i] = v;
    }
}

extern "C" void kernel_launch(void* const* d_in, const int* in_sizes, int n_in,
                              void* d_out, int out_size) {
    const float* traffic   = (const float*)d_in[0];
    const float* capacity  = (const float*)d_in[1];
    const int*   l2p       = (const int*)d_in[2];
    const int*   p2l       = (const int*)d_in[3];
    const float* pe_w1 = (const float*)d_in[4];
    const float* pe_b1 = (const float*)d_in[5];
    const float* pe_w2 = (const float*)d_in[6];
    const float* pe_b2 = (const float*)d_in[7];
    const float* le_w1 = (const float*)d_in[8];
    const float* le_b1 = (const float*)d_in[9];
    const float* le_w2 = (const float*)d_in[10];
    const float* le_b2 = (const float*)d_in[11];
    const float* gru_wih = (const float*)d_in[12];
    const float* gru_whh = (const float*)d_in[13];
    const float* gru_bih = (const float*)d_in[14];
    const float* gru_bhh = (const float*)d_in[15];
    const float* cell_wih = (const float*)d_in[16];
    const float* cell_whh = (const float*)d_in[17];
    const float* cell_bih = (const float*)d_in[18];
    const float* cell_bhh = (const float*)d_in[19];
    const float* am_w1 = (const float*)d_in[20];
    const float* am_b1 = (const float*)d_in[21];
    const float* am_w2 = (const float*)d_in[22];
    const float* am_b2 = (const float*)d_in[23];
    const float* am_w3 = (const float*)d_in[24];
    const float* am_b3 = (const float*)d_in[25];

    const size_t smem_mma = (size_t)(4 * 128 * PADK + 4 * 192 * PADK) * 2   // bf16 tiles
                          + (size_t)(128 * PADH + 2 * 192) * 4              // hold + biases
                          + (size_t)(128 * TMAX) * 4;                       // idx
    const size_t smem_grul = (size_t)(2 * 64 * 192 + 2 * 192 + 2 * 4 * 64) * 4;
    const size_t smem_l1 = (size_t)(256 * 128 + 128 + 4 * 256) * 4;
    const size_t smem_l2 = (size_t)(128 * 128 + 128 + 4 * 128) * 4;
    const size_t smem_l3 = (size_t)(128 * 64 + 64 + 4 * 128) * 4;

    cudaFuncSetAttribute(gru_path_mma, cudaFuncAttributeMaxDynamicSharedMemorySize, (int)smem_mma);
    cudaFuncSetAttribute(gru_link_kernel, cudaFuncAttributeMaxDynamicSharedMemorySize, (int)smem_grul);
    cudaFuncSetAttribute(matvec_relu<256, 128, 4, 0, 1>, cudaFuncAttributeMaxDynamicSharedMemorySize, (int)smem_l1);
    cudaFuncSetAttribute(matvec_relu<128, 128, 4, 1, 2>, cudaFuncAttributeMaxDynamicSharedMemorySize, (int)smem_l2);
    cudaFuncSetAttribute(matvec_relu<128, 64, 4, 2, 3>,  cudaFuncAttributeMaxDynamicSharedMemorySize, (int)smem_l3);

    prep_weights<<<48, 256>>>(gru_wih, gru_whh, gru_bih, gru_bhh);
    embed_kernel<0><<<1024, 256>>>(traffic, pe_w1, pe_b1, pe_w2, pe_b2, NPATH);
    embed_kernel<1><<<512, 256>>>(capacity, le_w1, le_b1, le_w2, le_b2, NLINK);

    const int gru_blocks = (NPATH + 127) / 128;   // 782

    for (int it = 0; it < NITERS; it++) {
        gru_path_mma<<<gru_blocks, 512, smem_mma>>>(l2p);
        agg_kernel<<<1024, 256>>>(p2l);
        matvec_relu<256, 128, 4, 0, 1><<<296, 128, smem_l1>>>(am_w1, am_b1, NLINK);
        matvec_relu<128, 128, 4, 1, 2><<<296, 128, smem_l2>>>(am_w2, am_b2, NLINK);
        matvec_relu<128, 64, 4, 2, 3><<<296, 64, smem_l3>>>(am_w3, am_b3, NLINK);
        gru_link_kernel<<<296, 256, smem_grul>>>(cell_wih, cell_whh, cell_bih, cell_bhh);
    }

    copy_out_kernel<<<4096, 256>>>((float*)d_out, out_size);
}

// round 8
// speedup vs baseline: 1.5938x; 1.0936x over previous
#include <cuda_runtime.h>
#include <cuda_bf16.h>
#include <math.h>
#include <stdint.h>

#define NPATH 100000
#define NLINK 20000
#define TMAX 8
#define NDEG 48
#define DS 64
#define NITERS 4
#define PADK 72   // bf16 row stride (36 words) -> conflict-free A-frag loads
#define WST 20    // packed-weight row stride in uint2 (conflict-free LDS.64)

// Persistent scratch: uninitialized __device__ globals.
__device__ float g_path_state[NPATH * DS];
__device__ float g_link_state[NLINK * DS];
__device__ float g_pss[NPATH * (TMAX + 1) * DS];
__device__ float g_agg[NLINK * 4 * DS];
__device__ float g_t1[NLINK * 128];
__device__ float g_t2[NLINK * 128];
__device__ float g_pa[NLINK * DS];
// Path-GRU weights: gate-permuted, bf16 hi/lo split, frag-packed uint2.
// Array a: 0=WihHi 1=WihLo 2=WhhHi 3=WhhLo; entry [a*192*WST + r*WST + kt*4 + tig]
__device__ uint2 g_wp[4 * 192 * WST];
__device__ float g_bih_p[192];
__device__ float g_bhh_p[192];

__device__ __forceinline__ void groupbar(int g) {
    asm volatile("bar.sync %0, 64;" :: "r"(g + 1) : "memory");
}
__device__ __forceinline__ float sigm(float x) { return 1.0f / (1.0f + expf(-x)); }

__device__ __forceinline__ uint32_t packbf(float f0, float f1) {
    __nv_bfloat162 v = __floats2bfloat162_rn(f0, f1);
    return *reinterpret_cast<uint32_t*>(&v);
}

__device__ __forceinline__ void mma16816(float* c, const uint32_t* a, uint32_t b0, uint32_t b1) {
    asm("mma.sync.aligned.m16n8k16.row.col.f32.bf16.bf16.f32 "
        "{%0,%1,%2,%3}, {%4,%5,%6,%7}, {%8,%9}, {%0,%1,%2,%3};"
        : "+f"(c[0]), "+f"(c[1]), "+f"(c[2]), "+f"(c[3])
        : "r"(a[0]), "r"(a[1]), "r"(a[2]), "r"(a[3]), "r"(b0), "r"(b1));
}

// ---------------------------------------------------------------------------
// Weight prep: gate-permute rows (chunk c = full r/z/n for units 8c..8c+7),
// split fp32 -> bf16 hi+lo, pack into per-thread MMA B fragments (uint2).
// Thread (r, kt, tig) packs k = {k0, k0+1, k0+8, k0+9}, k0 = kt*16+2*tig.
// ---------------------------------------------------------------------------
__global__ void prep_weights(const float* __restrict__ wih, const float* __restrict__ whh,
                             const float* __restrict__ bih, const float* __restrict__ bhh) {
    int i = blockIdx.x * blockDim.x + threadIdx.x;
    if (i < 192) {
        int c = i / 24, rem = i % 24, gate = rem >> 3, u = rem & 7;
        int ro = gate * 64 + c * 8 + u;
        g_bih_p[i] = bih[ro];
        g_bhh_p[i] = bhh[ro];
    }
    if (i < 192 * 16) {
        int r = i >> 4, rem2 = i & 15;
        int kt = rem2 >> 2, tig = rem2 & 3;
        int c = r / 24, rr = r % 24, gate = rr >> 3, u = rr & 7;
        int ro = gate * 64 + c * 8 + u;
        int k0 = kt * 16 + 2 * tig;
        const float* wi = wih + ro * 64;
        const float* wh = whh + ro * 64;
        float fi[4] = { wi[k0], wi[k0 + 1], wi[k0 + 8], wi[k0 + 9] };
        float fh[4] = { wh[k0], wh[k0 + 1], wh[k0 + 8], wh[k0 + 9] };
        float hi_i[4], hi_h[4];
#pragma unroll
        for (int q = 0; q < 4; q++) {
            hi_i[q] = __bfloat162float(__float2bfloat16(fi[q]));
            hi_h[q] = __bfloat162float(__float2bfloat16(fh[q]));
        }
        int o = r * WST + kt * 4 + tig;
        uint2 v;
        v.x = packbf(fi[0], fi[1]);                     v.y = packbf(fi[2], fi[3]);
        g_wp[0 * 192 * WST + o] = v;
        v.x = packbf(fi[0] - hi_i[0], fi[1] - hi_i[1]); v.y = packbf(fi[2] - hi_i[2], fi[3] - hi_i[3]);
        g_wp[1 * 192 * WST + o] = v;
        v.x = packbf(fh[0], fh[1]);                     v.y = packbf(fh[2], fh[3]);
        g_wp[2 * 192 * WST + o] = v;
        v.x = packbf(fh[0] - hi_h[0], fh[1] - hi_h[1]); v.y = packbf(fh[2] - hi_h[2], fh[3] - hi_h[3]);
        g_wp[3 * 192 * WST + o] = v;
    }
}

// ---------------------------------------------------------------------------
// FUSED path GRU, N-split, packed-B. 512 threads = 16 warps: warp w owns
// M-rows [16*(w&7), +16) and N-half (w>>3) = chunks [4*nh, 4*nh+4).
// h carried as bf16 hi+lo in smem (hold reconstructed as hi+lo).
// ---------------------------------------------------------------------------
__global__ void __launch_bounds__(512, 1) gru_path_mma(const int* __restrict__ l2p) {
    extern __shared__ __align__(16) char smraw[];
    uint2* sW            = (uint2*)smraw;                 // [4][192][WST]
    __nv_bfloat16* sXh   = (__nv_bfloat16*)(sW + 4 * 192 * WST);  // [128][PADK]
    __nv_bfloat16* sXl   = sXh + 128 * PADK;
    __nv_bfloat16* sHh   = sXl + 128 * PADK;
    __nv_bfloat16* sHl   = sHh + 128 * PADK;
    float* sBih          = (float*)(sHl + 128 * PADK);    // [192]
    float* sBhh          = sBih + 192;                    // [192]
    int*   sIdx          = (int*)(sBhh + 192);            // [128][TMAX]

    int tid = threadIdx.x;
    int pbase = blockIdx.x * 128;

    // stage packed weights + biases (once)
    for (int i = tid; i < 4 * 192 * WST; i += 512) sW[i] = g_wp[i];
    if (tid < 192) { sBih[tid] = g_bih_p[tid]; sBhh[tid] = g_bhh_p[tid]; }

    // stage all step indices (coalesced)
    for (int i = tid; i < 128 * TMAX; i += 512) {
        int pl = i / TMAX, tt = i % TMAX;
        int p = pbase + pl;
        sIdx[pl * TMAX + tt] = (p < NPATH) ? l2p[p * TMAX + tt] : -1;
    }

    // stage h0 (split hi/lo) + write pss[p,0]
    for (int i = tid; i < 128 * 64; i += 512) {
        int pl = i >> 6, k = i & 63;
        int p = pbase + pl;
        float hv = 0.f;
        if (p < NPATH) {
            hv = g_path_state[p * 64 + k];
            g_pss[p * 576 + k] = hv;
        }
        __nv_bfloat16 hh = __float2bfloat16(hv);
        sHh[pl * PADK + k] = hh;
        sHl[pl * PADK + k] = __float2bfloat16(hv - __bfloat162float(hh));
    }
    __syncthreads();

    int warp = tid >> 5, lane = tid & 31;
    int mw = warp & 7, nh = warp >> 3;
    int gid = lane >> 2, tig = lane & 3;
    int row0 = mw * 16 + gid;
    int row1 = row0 + 8;

    for (int t = 0; t < TMAX; t++) {
        // gather x (link states), split hi/lo
        for (int i = tid; i < 128 * 64; i += 512) {
            int pl = i >> 6, k = i & 63;
            int idx = sIdx[pl * TMAX + t];
            float xv = (idx >= 0) ? g_link_state[idx * 64 + k] : 0.f;
            __nv_bfloat16 xh = __float2bfloat16(xv);
            sXh[pl * PADK + k] = xh;
            sXl[pl * PADK + k] = __float2bfloat16(xv - __bfloat162float(xh));
        }
        __syncthreads();   // gather + prev-epilogue h-writes visible

        // cache A fragments (x hi/lo, h hi/lo; 4 k-tiles) — conflict-free LDS.32
        uint32_t aXh[4][4], aXl[4][4], aHh[4][4], aHl[4][4];
#pragma unroll
        for (int kt = 0; kt < 4; kt++) {
            int kb = kt * 16 + 2 * tig;
            const __nv_bfloat16 *r0p, *r1p;
            r0p = sXh + row0 * PADK + kb; r1p = sXh + row1 * PADK + kb;
            aXh[kt][0] = *(const uint32_t*)(r0p);
            aXh[kt][1] = *(const uint32_t*)(r1p);
            aXh[kt][2] = *(const uint32_t*)(r0p + 8);
            aXh[kt][3] = *(const uint32_t*)(r1p + 8);
            r0p = sXl + row0 * PADK + kb; r1p = sXl + row1 * PADK + kb;
            aXl[kt][0] = *(const uint32_t*)(r0p);
            aXl[kt][1] = *(const uint32_t*)(r1p);
            aXl[kt][2] = *(const uint32_t*)(r0p + 8);
            aXl[kt][3] = *(const uint32_t*)(r1p + 8);
            r0p = sHh + row0 * PADK + kb; r1p = sHh + row1 * PADK + kb;
            aHh[kt][0] = *(const uint32_t*)(r0p);
            aHh[kt][1] = *(const uint32_t*)(r1p);
            aHh[kt][2] = *(const uint32_t*)(r0p + 8);
            aHh[kt][3] = *(const uint32_t*)(r1p + 8);
            r0p = sHl + row0 * PADK + kb; r1p = sHl + row1 * PADK + kb;
            aHl[kt][0] = *(const uint32_t*)(r0p);
            aHl[kt][1] = *(const uint32_t*)(r1p);
            aHl[kt][2] = *(const uint32_t*)(r0p + 8);
            aHl[kt][3] = *(const uint32_t*)(r1p + 8);
        }
        __syncthreads();   // all h-frag reads done before epilogue rewrites sH

        for (int c = nh * 4; c < nh * 4 + 4; c++) {
            float ci[3][4], ch[3][4];
#pragma unroll
            for (int j = 0; j < 3; j++) {
                int nb = c * 24 + j * 8 + 2 * tig;
                float b0 = sBih[nb], b1 = sBih[nb + 1];
                ci[j][0] = b0; ci[j][1] = b1; ci[j][2] = b0; ci[j][3] = b1;
                float d0 = sBhh[nb], d1 = sBhh[nb + 1];
                ch[j][0] = d0; ch[j][1] = d1; ch[j][2] = d0; ch[j][3] = d1;
            }
#pragma unroll
            for (int kt = 0; kt < 4; kt++) {
#pragma unroll
                for (int j = 0; j < 3; j++) {
                    int o = (c * 24 + j * 8 + gid) * WST + kt * 4 + tig;
                    uint2 wA = sW[0 * 192 * WST + o];   // WihHi
                    uint2 wB = sW[1 * 192 * WST + o];   // WihLo
                    uint2 wC = sW[2 * 192 * WST + o];   // WhhHi
                    uint2 wD = sW[3 * 192 * WST + o];   // WhhLo
                    mma16816(ci[j], aXh[kt], wA.x, wA.y);
                    mma16816(ci[j], aXl[kt], wA.x, wA.y);
                    mma16816(ci[j], aXh[kt], wB.x, wB.y);
                    mma16816(ch[j], aHh[kt], wC.x, wC.y);
                    mma16816(ch[j], aHl[kt], wC.x, wC.y);
                    mma16816(ch[j], aHh[kt], wD.x, wD.y);
                }
            }
            // epilogue: per-thread GRU update, 2 rows x 2 units
#pragma unroll
            for (int half = 0; half < 2; half++) {
                int lrow = (half == 0) ? row0 : row1;
                int p = pbase + lrow;
                int valid = sIdx[lrow * TMAX + t] >= 0;
                int ri = half * 2;
                int ubase = c * 8 + 2 * tig;
                uint32_t hhp = *(uint32_t*)(sHh + lrow * PADK + ubase);
                uint32_t hlp = *(uint32_t*)(sHl + lrow * PADK + ubase);
                __nv_bfloat162 hh2 = *(__nv_bfloat162*)&hhp;
                __nv_bfloat162 hl2 = *(__nv_bfloat162*)&hlp;
                float hold0 = __bfloat162float(hh2.x) + __bfloat162float(hl2.x);
                float hold1 = __bfloat162float(hh2.y) + __bfloat162float(hl2.y);
                float r0 = sigm(ci[0][ri] + ch[0][ri]);
                float z0 = sigm(ci[1][ri] + ch[1][ri]);
                float n0 = tanhf(ci[2][ri] + r0 * ch[2][ri]);
                float hn0 = valid ? ((1.f - z0) * n0 + z0 * hold0) : hold0;
                float r1 = sigm(ci[0][ri + 1] + ch[0][ri + 1]);
                float z1 = sigm(ci[1][ri + 1] + ch[1][ri + 1]);
                float n1 = tanhf(ci[2][ri + 1] + r1 * ch[2][ri + 1]);
                float hn1 = valid ? ((1.f - z1) * n1 + z1 * hold1) : hold1;
                float h0f = __bfloat162float(__float2bfloat16(hn0));
                float h1f = __bfloat162float(__float2bfloat16(hn1));
                *(uint32_t*)(sHh + lrow * PADK + ubase) = packbf(hn0, hn1);
                *(uint32_t*)(sHl + lrow * PADK + ubase) = packbf(hn0 - h0f, hn1 - h1f);
                if (p < NPATH) {
                    float2 o2 = make_float2(valid ? hn0 : 0.f, valid ? hn1 : 0.f);
                    *(float2*)(g_pss + p * 576 + (t + 1) * 64 + ubase) = o2;
                }
            }
        }
        __syncthreads();   // epilogue h-writes complete before next step
    }

    // final path_state writeback (coalesced; h = hi + lo)
    for (int i = tid; i < 128 * 64; i += 512) {
        int pl = i >> 6, k = i & 63;
        int p = pbase + pl;
        if (p < NPATH)
            g_path_state[p * 64 + k] =
                __bfloat162float(sHh[pl * PADK + k]) + __bfloat162float(sHl[pl * PADK + k]);
    }
}

// ---------------------------------------------------------------------------
// Embedding
// ---------------------------------------------------------------------------
template <int TARGET>
__global__ void embed_kernel(const float* __restrict__ x,
                             const float* __restrict__ w1, const float* __restrict__ b1,
                             const float* __restrict__ w2, const float* __restrict__ b2,
                             int n) {
    __shared__ float sWm[64 * 64];
    __shared__ float sw1[64], sb1[64], sb2[64];
    __shared__ float sh1[4][64];
    float* st = (TARGET == 0) ? g_path_state : g_link_state;
    int tid = threadIdx.x;
    for (int i = tid; i < 4096; i += 256) {
        int j = i >> 6, k = i & 63;
        sWm[k * 64 + j] = w2[i];
    }
    if (tid < 64) { sw1[tid] = w1[tid]; sb1[tid] = b1[tid]; sb2[tid] = b2[tid]; }
    __syncthreads();
    int g = tid >> 6, d = tid & 63;
    for (int base = blockIdx.x * 4; base < n; base += gridDim.x * 4) {
        int p = base + g;
        float h1 = 0.0f;
        if (p < n) {
            float t = x[p];
            h1 = fmaxf(t * sw1[d] + sb1[d], 0.0f);
        }
        sh1[g][d] = h1;
        groupbar(g);
        float acc = sb2[d];
#pragma unroll 8
        for (int k = 0; k < 64; k++) acc += sh1[g][k] * sWm[k * 64 + d];
        if (p < n) st[p * 64 + d] = fmaxf(acc, 0.0f);
        groupbar(g);
    }
}

// ---------------------------------------------------------------------------
// Link aggregation
// ---------------------------------------------------------------------------
__global__ void agg_kernel(const int* __restrict__ p2l) {
    __shared__ int s_pi[4][NDEG], s_pos[4][NDEG];
    int tid = threadIdx.x;
    int g = tid >> 6, d = tid & 63;
    for (int base = blockIdx.x * 4; base < NLINK; base += gridDim.x * 4) {
        int l = base + g;
        if (l < NLINK && d < NDEG) {
            s_pi[g][d]  = p2l[(l * NDEG + d) * 2];
            s_pos[g][d] = p2l[(l * NDEG + d) * 2 + 1];
        }
        groupbar(g);
        if (l < NLINK) {
            float vmin = INFINITY, vmax = -INFINITY, vsum = 0.0f;
            int cnt = 0;
            for (int e = 0; e < NDEG; e++) {
                int pi = s_pi[g][e];
                if (pi < 0) continue;
                cnt++;
                float v = g_pss[(pi * 9 + s_pos[g][e]) * 64 + d];
                vmin = fminf(vmin, v);
                vmax = fmaxf(vmax, v);
                vsum += v;
            }
            float mean = vsum / (float)(cnt > 0 ? cnt : 1);
            g_agg[l * 256 + d]        = vmin;
            g_agg[l * 256 + 64 + d]   = vmax;
            g_agg[l * 256 + 128 + d]  = vsum;
            g_agg[l * 256 + 192 + d]  = mean;
        }
        groupbar(g);
    }
}

// ---------------------------------------------------------------------------
// Grouped batched matvec + relu: GR groups of OUT threads share smem weights.
// SRC/DST: 0=g_agg,1=g_t1,2=g_t2,3=g_pa.
// ---------------------------------------------------------------------------
__device__ __forceinline__ float* buf_sel(int s) {
    if (s == 0) return g_agg;
    if (s == 1) return g_t1;
    if (s == 2) return g_t2;
    return g_pa;
}

template <int IN, int OUT, int NL, int GR, int SRC, int DST>
__global__ void matvec_relu(const float* __restrict__ W,
                            const float* __restrict__ b, int n) {
    extern __shared__ float sm[];
    float* sWT = sm;                 // [IN][OUT]
    float* sb  = sWT + IN * OUT;     // OUT
    float* sin = sb + OUT;           // [GR][NL*IN]
    const float* in = buf_sel(SRC);
    float* out = buf_sel(DST);
    int tid = threadIdx.x;
    const int NTH = OUT * GR;
    for (int i = tid; i < IN * OUT; i += NTH) {
        int j = i / IN, k = i % IN;
        sWT[k * OUT + j] = W[i];
    }
    if (tid < OUT) sb[tid] = b[tid];
    __syncthreads();
    int g = tid / OUT, j = tid % OUT;
    float* gin = sin + g * NL * IN;
    for (int l0 = (blockIdx.x * GR + g) * NL; l0 < n; l0 += gridDim.x * GR * NL) {
        for (int i = j; i < NL * IN; i += OUT) {
            int ll = l0 + i / IN;
            gin[i] = (ll < n) ? in[ll * IN + (i % IN)] : 0.0f;
        }
        asm volatile("bar.sync %0, %1;" :: "r"(g + 1), "r"(OUT) : "memory");
        float acc[NL];
#pragma unroll
        for (int q = 0; q < NL; q++) acc[q] = sb[j];
#pragma unroll 4
        for (int k = 0; k < IN; k++) {
            float w = sWT[k * OUT + j];
#pragma unroll
            for (int q = 0; q < NL; q++) acc[q] += gin[q * IN + k] * w;
        }
#pragma unroll
        for (int q = 0; q < NL; q++) {
            int ll = l0 + q;
            if (ll < n) out[ll * OUT + j] = fmaxf(acc[q], 0.0f);
        }
        asm volatile("bar.sync %0, %1;" :: "r"(g + 1), "r"(OUT) : "memory");
    }
}

// ---------------------------------------------------------------------------
// Link GRU cell
// ---------------------------------------------------------------------------
__global__ void gru_link_kernel(const float* __restrict__ wih, const float* __restrict__ whh,
                                const float* __restrict__ bih, const float* __restrict__ bhh) {
    extern __shared__ float sm[];
    float* sWi = sm;
    float* sWh = sWi + 64 * 192;
    float* sbi = sWh + 64 * 192;
    float* sbh = sbi + 192;
    float* sx  = sbh + 192;
    float* sh  = sx + 4 * 64;
    int tid = threadIdx.x;
    for (int i = tid; i < 192 * 64; i += 256) {
        int j = i / 64, k = i % 64;
        sWi[k * 192 + j] = wih[i];
        sWh[k * 192 + j] = whh[i];
    }
    for (int i = tid; i < 192; i += 256) { sbi[i] = bih[i]; sbh[i] = bhh[i]; }
    __syncthreads();
    int g = tid >> 6, d = tid & 63;
    float* gx = sx + g * 64;
    float* gh = sh + g * 64;
    for (int base = blockIdx.x * 4; base < NLINK; base += gridDim.x * 4) {
        int l = base + g;
        bool e = l < NLINK;
        float hd = 0.0f;
        if (e) {
            gx[d] = g_pa[l * 64 + d];
            hd = g_link_state[l * 64 + d];
            gh[d] = hd;
        } else { gx[d] = 0.0f; gh[d] = 0.0f; }
        groupbar(g);
        float ar = sbi[d], az = sbi[64 + d], an = sbi[128 + d];
        float cr = sbh[d], cz = sbh[64 + d], cn = sbh[128 + d];
#pragma unroll 8
        for (int k = 0; k < 64; k++) {
            float xk = gx[k], hk = gh[k];
            const float* wi = sWi + k * 192;
            const float* wh = sWh + k * 192;
            ar += xk * wi[d];       az += xk * wi[64 + d];  an += xk * wi[128 + d];
            cr += hk * wh[d];       cz += hk * wh[64 + d];  cn += hk * wh[128 + d];
        }
        groupbar(g);
        if (e) {
            float r = sigm(ar + cr);
            float z = sigm(az + cz);
            float nn = tanhf(an + r * cn);
            g_link_state[l * 64 + d] = (1.0f - z) * nn + z * hd;
        }
        groupbar(g);
    }
}

__global__ void copy_out_kernel(float* __restrict__ out, int out_size) {
    const int n1 = NPATH * DS;
    const int n2 = n1 + NLINK * DS;
    for (int i = blockIdx.x * blockDim.x + threadIdx.x; i < out_size;
         i += gridDim.x * blockDim.x) {
        float v = 0.0f;
        if (i < n1) v = g_path_state[i];
        else if (i < n2) v = g_link_state[i - n1];
        out[i] = v;
    }
}

extern "C" void kernel_launch(void* const* d_in, const int* in_sizes, int n_in,
                              void* d_out, int out_size) {
    const float* traffic   = (const float*)d_in[0];
    const float* capacity  = (const float*)d_in[1];
    const int*   l2p       = (const int*)d_in[2];
    const int*   p2l       = (const int*)d_in[3];
    const float* pe_w1 = (const float*)d_in[4];
    const float* pe_b1 = (const float*)d_in[5];
    const float* pe_w2 = (const float*)d_in[6];
    const float* pe_b2 = (const float*)d_in[7];
    const float* le_w1 = (const float*)d_in[8];
    const float* le_b1 = (const float*)d_in[9];
    const float* le_w2 = (const float*)d_in[10];
    const float* le_b2 = (const float*)d_in[11];
    const float* gru_wih = (const float*)d_in[12];
    const float* gru_whh = (const float*)d_in[13];
    const float* gru_bih = (const float*)d_in[14];
    const float* gru_bhh = (const float*)d_in[15];
    const float* cell_wih = (const float*)d_in[16];
    const float* cell_whh = (const float*)d_in[17];
    const float* cell_bih = (const float*)d_in[18];
    const float* cell_bhh = (const float*)d_in[19];
    const float* am_w1 = (const float*)d_in[20];
    const float* am_b1 = (const float*)d_in[21];
    const float* am_w2 = (const float*)d_in[22];
    const float* am_b2 = (const float*)d_in[23];
    const float* am_w3 = (const float*)d_in[24];
    const float* am_b3 = (const float*)d_in[25];

    const size_t smem_mma = (size_t)(4 * 192 * WST) * 8        // packed weights
                          + (size_t)(4 * 128 * PADK) * 2       // X/H hi/lo bf16 tiles
                          + (size_t)(2 * 192) * 4              // biases
                          + (size_t)(128 * TMAX) * 4;          // idx
    const size_t smem_grul = (size_t)(2 * 64 * 192 + 2 * 192 + 2 * 4 * 64) * 4;
    const size_t smem_l1 = (size_t)(256 * 128 + 128 + 4 * 8 * 256) * 4;
    const size_t smem_l2 = (size_t)(128 * 128 + 128 + 4 * 8 * 128) * 4;
    const size_t smem_l3 = (size_t)(128 * 64 + 64 + 8 * 8 * 128) * 4;

    cudaFuncSetAttribute(gru_path_mma, cudaFuncAttributeMaxDynamicSharedMemorySize, (int)smem_mma);
    cudaFuncSetAttribute(gru_link_kernel, cudaFuncAttributeMaxDynamicSharedMemorySize, (int)smem_grul);
    cudaFuncSetAttribute(matvec_relu<256, 128, 8, 4, 0, 1>, cudaFuncAttributeMaxDynamicSharedMemorySize, (int)smem_l1);
    cudaFuncSetAttribute(matvec_relu<128, 128, 8, 4, 1, 2>, cudaFuncAttributeMaxDynamicSharedMemorySize, (int)smem_l2);
    cudaFuncSetAttribute(matvec_relu<128, 64, 8, 8, 2, 3>,  cudaFuncAttributeMaxDynamicSharedMemorySize, (int)smem_l3);

    prep_weights<<<12, 256>>>(gru_wih, gru_whh, gru_bih, gru_bhh);
    embed_kernel<0><<<1024, 256>>>(traffic, pe_w1, pe_b1, pe_w2, pe_b2, NPATH);
    embed_kernel<1><<<512, 256>>>(capacity, le_w1, le_b1, le_w2, le_b2, NLINK);

    const int gru_blocks = (NPATH + 127) / 128;   // 782

    for (int it = 0; it < NITERS; it++) {
        gru_path_mma<<<gru_blocks, 512, smem_mma>>>(l2p);
        agg_kernel<<<1024, 256>>>(p2l);
        matvec_relu<256, 128, 8, 4, 0, 1><<<625, 512, smem_l1>>>(am_w1, am_b1, NLINK);
        matvec_relu<128, 128, 8, 4, 1, 2><<<625, 512, smem_l2>>>(am_w2, am_b2, NLINK);
        matvec_relu<128, 64, 8, 8, 2, 3><<<313, 512, smem_l3>>>(am_w3, am_b3, NLINK);
        gru_link_kernel<<<296, 256, smem_grul>>>(cell_wih, cell_whh, cell_bih, cell_bhh);
    }

    copy_out_kernel<<<4096, 256>>>((float*)d_out, out_size);
}

// round 10
// speedup vs baseline: 2.1151x; 1.3271x over previous
#include <cuda_runtime.h>
#include <cuda_bf16.h>
#include <math.h>
#include <stdint.h>

#define NPATH 100000
#define NLINK 20000
#define TMAX 8
#define NDEG 48
#define DS 64
#define NITERS 4
#define PADK 72   // bf16 H-tile row stride
#define PADX 68   // fp32 X/H-tile row stride (16B-aligned rows)
#define WST 20    // packed-weight row stride in uint2

// Persistent scratch: uninitialized __device__ globals.
__device__ float g_path_state[NPATH * DS];
__device__ float g_link_state[NLINK * DS];
__device__ float g_pss[NPATH * (TMAX + 1) * DS];
__device__ float g_agg[NLINK * 4 * DS];
__device__ float g_t1[NLINK * 128];
__device__ float g_t2[NLINK * 128];
__device__ float g_pa[NLINK * DS];
// Packed GRU weights (path + cell): gate-permuted, bf16 hi/lo, frag-ready uint2.
__device__ uint2 g_wp[4 * 192 * WST];    // path GRU
__device__ uint2 g_wpc[4 * 192 * WST];   // link (cell) GRU
__device__ float g_bih_p[192], g_bhh_p[192];
__device__ float g_bihc_p[192], g_bhhc_p[192];

__device__ __forceinline__ void groupbar(int g) {
    asm volatile("bar.sync %0, 64;" :: "r"(g + 1) : "memory");
}
__device__ __forceinline__ float fsigm(float x) {
    return __fdividef(1.0f, 1.0f + __expf(-x));
}
__device__ __forceinline__ float ftanh(float x) {
    x = fminf(fmaxf(x, -15.0f), 15.0f);
    float e = __expf(-2.0f * x);
    return __fdividef(1.0f - e, 1.0f + e);
}

__device__ __forceinline__ uint32_t packbf(float f0, float f1) {
    __nv_bfloat162 v = __floats2bfloat162_rn(f0, f1);
    return *reinterpret_cast<uint32_t*>(&v);
}
// split float2 -> bf16x2 hi + bf16x2 lo
__device__ __forceinline__ void split2(float2 v, uint32_t& hi, uint32_t& lo) {
    __nv_bfloat162 h = __floats2bfloat162_rn(v.x, v.y);
    hi = *reinterpret_cast<uint32_t*>(&h);
    lo = packbf(v.x - __bfloat162float(h.x), v.y - __bfloat162float(h.y));
}

__device__ __forceinline__ void mma16816(float* c, const uint32_t* a, uint32_t b0, uint32_t b1) {
    asm("mma.sync.aligned.m16n8k16.row.col.f32.bf16.bf16.f32 "
        "{%0,%1,%2,%3}, {%4,%5,%6,%7}, {%8,%9}, {%0,%1,%2,%3};"
        : "+f"(c[0]), "+f"(c[1]), "+f"(c[2]), "+f"(c[3])
        : "r"(a[0]), "r"(a[1]), "r"(a[2]), "r"(a[3]), "r"(b0), "r"(b1));
}

// ---------------------------------------------------------------------------
// Weight prep (path + cell): gate-permute, bf16 hi/lo split, frag-pack.
// ---------------------------------------------------------------------------
__device__ __forceinline__ void pack_w(const float* __restrict__ wih,
                                       const float* __restrict__ whh,
                                       uint2* dst, int i) {
    int r = i >> 4, rem2 = i & 15;
    int kt = rem2 >> 2, tig = rem2 & 3;
    int c = r / 24, rr = r % 24, gate = rr >> 3, u = rr & 7;
    int ro = gate * 64 + c * 8 + u;
    int k0 = kt * 16 + 2 * tig;
    const float* wi = wih + ro * 64;
    const float* wh = whh + ro * 64;
    float fi[4] = { wi[k0], wi[k0 + 1], wi[k0 + 8], wi[k0 + 9] };
    float fh[4] = { wh[k0], wh[k0 + 1], wh[k0 + 8], wh[k0 + 9] };
    float hi_i[4], hi_h[4];
#pragma unroll
    for (int q = 0; q < 4; q++) {
        hi_i[q] = __bfloat162float(__float2bfloat16(fi[q]));
        hi_h[q] = __bfloat162float(__float2bfloat16(fh[q]));
    }
    int o = r * WST + kt * 4 + tig;
    uint2 v;
    v.x = packbf(fi[0], fi[1]);                     v.y = packbf(fi[2], fi[3]);
    dst[0 * 192 * WST + o] = v;
    v.x = packbf(fi[0] - hi_i[0], fi[1] - hi_i[1]); v.y = packbf(fi[2] - hi_i[2], fi[3] - hi_i[3]);
    dst[1 * 192 * WST + o] = v;
    v.x = packbf(fh[0], fh[1]);                     v.y = packbf(fh[2], fh[3]);
    dst[2 * 192 * WST + o] = v;
    v.x = packbf(fh[0] - hi_h[0], fh[1] - hi_h[1]); v.y = packbf(fh[2] - hi_h[2], fh[3] - hi_h[3]);
    dst[3 * 192 * WST + o] = v;
}

__global__ void prep_weights(const float* __restrict__ wih, const float* __restrict__ whh,
                             const float* __restrict__ bih, const float* __restrict__ bhh,
                             const float* __restrict__ cwih, const float* __restrict__ cwhh,
                             const float* __restrict__ cbih, const float* __restrict__ cbhh) {
    int i = blockIdx.x * blockDim.x + threadIdx.x;
    if (i < 192) {
        int c = i / 24, rem = i % 24, gate = rem >> 3, u = rem & 7;
        int ro = gate * 64 + c * 8 + u;
        g_bih_p[i] = bih[ro];   g_bhh_p[i] = bhh[ro];
        g_bihc_p[i] = cbih[ro]; g_bhhc_p[i] = cbhh[ro];
    }
    if (i < 3072) pack_w(wih, whh, g_wp, i);
    else if (i >= 4096 && i < 7168) pack_w(cwih, cwhh, g_wpc, i - 4096);
}

// ---------------------------------------------------------------------------
// cp.async gather of one timestep's x rows into fp32 X tile (zero-fill invalid)
// ---------------------------------------------------------------------------
__device__ __forceinline__ void gather_async(float* sX, const int* sIdx, int t, int tid) {
    for (int i = tid; i < 128 * 16; i += 512) {
        int pl = i >> 4, q = i & 15;
        int idx = sIdx[pl * TMAX + t];
        const float* src = g_link_state + (idx >= 0 ? idx : 0) * 64 + q * 4;
        uint32_t dst = (uint32_t)__cvta_generic_to_shared(sX + pl * PADX + q * 4);
        int sz = (idx >= 0) ? 16 : 0;
        asm volatile("cp.async.ca.shared.global [%0], [%1], 16, %2;"
                     :: "r"(dst), "l"(src), "r"(sz) : "memory");
    }
}

// ---------------------------------------------------------------------------
// FUSED path GRU, N-split, cp.async-pipelined. 512 threads = 16 warps.
// Warp w: M-rows [16*(w&7), +16), N-half (w>>3) = chunks [4*nh, +4).
// ---------------------------------------------------------------------------
__global__ void __launch_bounds__(512, 1) gru_path_mma(const int* __restrict__ l2p) {
    extern __shared__ __align__(16) char smraw[];
    uint2* sW          = (uint2*)smraw;                       // [4][192][WST]
    float* sX          = (float*)(sW + 4 * 192 * WST);        // [128][PADX] fp32
    __nv_bfloat16* sHh = (__nv_bfloat16*)(sX + 128 * PADX);   // [128][PADK]
    __nv_bfloat16* sHl = sHh + 128 * PADK;
    float* sBih        = (float*)(sHl + 128 * PADK);          // [192]
    float* sBhh        = sBih + 192;
    int*   sIdx        = (int*)(sBhh + 192);                  // [128][TMAX]

    int tid = threadIdx.x;
    int pbase = blockIdx.x * 128;

    // stage indices first (gather depends on them)
    for (int i = tid; i < 128 * TMAX; i += 512) {
        int pl = i / TMAX, tt = i % TMAX;
        int p = pbase + pl;
        sIdx[pl * TMAX + tt] = (p < NPATH) ? l2p[p * TMAX + tt] : -1;
    }
    __syncthreads();

    // issue gather(0) while staging everything else
    gather_async(sX, sIdx, 0, tid);
    asm volatile("cp.async.commit_group;" ::: "memory");

    for (int i = tid; i < 4 * 192 * WST; i += 512) sW[i] = g_wp[i];
    if (tid < 192) { sBih[tid] = g_bih_p[tid]; sBhh[tid] = g_bhh_p[tid]; }

    for (int i = tid; i < 128 * 64; i += 512) {
        int pl = i >> 6, k = i & 63;
        int p = pbase + pl;
        float hv = 0.f;
        if (p < NPATH) {
            hv = g_path_state[p * 64 + k];
            g_pss[p * 576 + k] = hv;
        }
        __nv_bfloat16 hh = __float2bfloat16(hv);
        sHh[pl * PADK + k] = hh;
        sHl[pl * PADK + k] = __float2bfloat16(hv - __bfloat162float(hh));
    }
    asm volatile("cp.async.wait_group 0;" ::: "memory");
    __syncthreads();

    int warp = tid >> 5, lane = tid & 31;
    int mw = warp & 7, nh = warp >> 3;
    int gid = lane >> 2, tig = lane & 3;
    int row0 = mw * 16 + gid;
    int row1 = row0 + 8;

    for (int t = 0; t < TMAX; t++) {
        // build A fragments: X from fp32 tile (split in regs), H from bf16 tiles
        uint32_t aXh[4][4], aXl[4][4], aHh[4][4], aHl[4][4];
#pragma unroll
        for (int kt = 0; kt < 4; kt++) {
            int kb = kt * 16 + 2 * tig;
            float2 v;
            v = *(float2*)(sX + row0 * PADX + kb);     split2(v, aXh[kt][0], aXl[kt][0]);
            v = *(float2*)(sX + row1 * PADX + kb);     split2(v, aXh[kt][1], aXl[kt][1]);
            v = *(float2*)(sX + row0 * PADX + kb + 8); split2(v, aXh[kt][2], aXl[kt][2]);
            v = *(float2*)(sX + row1 * PADX + kb + 8); split2(v, aXh[kt][3], aXl[kt][3]);
            const __nv_bfloat16 *r0p, *r1p;
            r0p = sHh + row0 * PADK + kb; r1p = sHh + row1 * PADK + kb;
            aHh[kt][0] = *(const uint32_t*)(r0p);
            aHh[kt][1] = *(const uint32_t*)(r1p);
            aHh[kt][2] = *(const uint32_t*)(r0p + 8);
            aHh[kt][3] = *(const uint32_t*)(r1p + 8);
            r0p = sHl + row0 * PADK + kb; r1p = sHl + row1 * PADK + kb;
            aHl[kt][0] = *(const uint32_t*)(r0p);
            aHl[kt][1] = *(const uint32_t*)(r1p);
            aHl[kt][2] = *(const uint32_t*)(r0p + 8);
            aHl[kt][3] = *(const uint32_t*)(r1p + 8);
        }
        __syncthreads();   // frag reads done: X tile free for prefetch, H tiles free for epilogue

        if (t + 1 < TMAX) gather_async(sX, sIdx, t + 1, tid);
        asm volatile("cp.async.commit_group;" ::: "memory");

        for (int c = nh * 4; c < nh * 4 + 4; c++) {
            float ci[3][4], ch[3][4];
#pragma unroll
            for (int j = 0; j < 3; j++) {
                int nb = c * 24 + j * 8 + 2 * tig;
                float b0 = sBih[nb], b1 = sBih[nb + 1];
                ci[j][0] = b0; ci[j][1] = b1; ci[j][2] = b0; ci[j][3] = b1;
                float d0 = sBhh[nb], d1 = sBhh[nb + 1];
                ch[j][0] = d0; ch[j][1] = d1; ch[j][2] = d0; ch[j][3] = d1;
            }
#pragma unroll
            for (int kt = 0; kt < 4; kt++) {
#pragma unroll
                for (int j = 0; j < 3; j++) {
                    int o = (c * 24 + j * 8 + gid) * WST + kt * 4 + tig;
                    uint2 wA = sW[0 * 192 * WST + o];
                    uint2 wB = sW[1 * 192 * WST + o];
                    uint2 wC = sW[2 * 192 * WST + o];
                    uint2 wD = sW[3 * 192 * WST + o];
                    mma16816(ci[j], aXh[kt], wA.x, wA.y);
                    mma16816(ci[j], aXl[kt], wA.x, wA.y);
                    mma16816(ci[j], aXh[kt], wB.x, wB.y);
                    mma16816(ch[j], aHh[kt], wC.x, wC.y);
                    mma16816(ch[j], aHl[kt], wC.x, wC.y);
                    mma16816(ch[j], aHh[kt], wD.x, wD.y);
                }
            }
#pragma unroll
            for (int half = 0; half < 2; half++) {
                int lrow = (half == 0) ? row0 : row1;
                int p = pbase + lrow;
                int valid = sIdx[lrow * TMAX + t] >= 0;
                int ri = half * 2;
                int ubase = c * 8 + 2 * tig;
                uint32_t hhp = *(uint32_t*)(sHh + lrow * PADK + ubase);
                uint32_t hlp = *(uint32_t*)(sHl + lrow * PADK + ubase);
                __nv_bfloat162 hh2 = *(__nv_bfloat162*)&hhp;
                __nv_bfloat162 hl2 = *(__nv_bfloat162*)&hlp;
                float hold0 = __bfloat162float(hh2.x) + __bfloat162float(hl2.x);
                float hold1 = __bfloat162float(hh2.y) + __bfloat162float(hl2.y);
                float r0 = fsigm(ci[0][ri] + ch[0][ri]);
                float z0 = fsigm(ci[1][ri] + ch[1][ri]);
                float n0 = ftanh(ci[2][ri] + r0 * ch[2][ri]);
                float hn0 = valid ? ((1.f - z0) * n0 + z0 * hold0) : hold0;
                float r1 = fsigm(ci[0][ri + 1] + ch[0][ri + 1]);
                float z1 = fsigm(ci[1][ri + 1] + ch[1][ri + 1]);
                float n1 = ftanh(ci[2][ri + 1] + r1 * ch[2][ri + 1]);
                float hn1 = valid ? ((1.f - z1) * n1 + z1 * hold1) : hold1;
                float h0f = __bfloat162float(__float2bfloat16(hn0));
                float h1f = __bfloat162float(__float2bfloat16(hn1));
                *(uint32_t*)(sHh + lrow * PADK + ubase) = packbf(hn0, hn1);
                *(uint32_t*)(sHl + lrow * PADK + ubase) = packbf(hn0 - h0f, hn1 - h1f);
                if (p < NPATH) {
                    float2 o2 = make_float2(valid ? hn0 : 0.f, valid ? hn1 : 0.f);
                    *(float2*)(g_pss + p * 576 + (t + 1) * 64 + ubase) = o2;
                }
            }
        }
        asm volatile("cp.async.wait_group 0;" ::: "memory");
        __syncthreads();   // epilogue h-writes + prefetched X visible
    }

    for (int i = tid; i < 128 * 64; i += 512) {
        int pl = i >> 6, k = i & 63;
        int p = pbase + pl;
        if (p < NPATH)
            g_path_state[p * 64 + k] =
                __bfloat162float(sHh[pl * PADK + k]) + __bfloat162float(sHl[pl * PADK + k]);
    }
}

// ---------------------------------------------------------------------------
// Link GRU via MMA: one step, dense. x = g_pa, h = g_link_state (in/out).
// ---------------------------------------------------------------------------
__global__ void __launch_bounds__(512, 1) gru_link_mma() {
    extern __shared__ __align__(16) char smraw[];
    uint2* sW   = (uint2*)smraw;                      // [4][192][WST]
    float* sX   = (float*)(sW + 4 * 192 * WST);       // [128][PADX]
    float* sH   = sX + 128 * PADX;                    // [128][PADX]
    float* sBih = sH + 128 * PADX;                    // [192]
    float* sBhh = sBih + 192;

    int tid = threadIdx.x;
    int lbase = blockIdx.x * 128;

    for (int i = tid; i < 4 * 192 * WST; i += 512) sW[i] = g_wpc[i];
    if (tid < 192) { sBih[tid] = g_bihc_p[tid]; sBhh[tid] = g_bhhc_p[tid]; }
    for (int i = tid; i < 128 * 64; i += 512) {
        int pl = i >> 6, k = i & 63;
        int l = lbase + pl;
        sX[pl * PADX + k] = (l < NLINK) ? g_pa[l * 64 + k] : 0.f;
        sH[pl * PADX + k] = (l < NLINK) ? g_link_state[l * 64 + k] : 0.f;
    }
    __syncthreads();

    int warp = tid >> 5, lane = tid & 31;
    int mw = warp & 7, nh = warp >> 3;
    int gid = lane >> 2, tig = lane & 3;
    int row0 = mw * 16 + gid;
    int row1 = row0 + 8;

    uint32_t aXh[4][4], aXl[4][4], aHh[4][4], aHl[4][4];
#pragma unroll
    for (int kt = 0; kt < 4; kt++) {
        int kb = kt * 16 + 2 * tig;
        float2 v;
        v = *(float2*)(sX + row0 * PADX + kb);     split2(v, aXh[kt][0], aXl[kt][0]);
        v = *(float2*)(sX + row1 * PADX + kb);     split2(v, aXh[kt][1], aXl[kt][1]);
        v = *(float2*)(sX + row0 * PADX + kb + 8); split2(v, aXh[kt][2], aXl[kt][2]);
        v = *(float2*)(sX + row1 * PADX + kb + 8); split2(v, aXh[kt][3], aXl[kt][3]);
        v = *(float2*)(sH + row0 * PADX + kb);     split2(v, aHh[kt][0], aHl[kt][0]);
        v = *(float2*)(sH + row1 * PADX + kb);     split2(v, aHh[kt][1], aHl[kt][1]);
        v = *(float2*)(sH + row0 * PADX + kb + 8); split2(v, aHh[kt][2], aHl[kt][2]);
        v = *(float2*)(sH + row1 * PADX + kb + 8); split2(v, aHh[kt][3], aHl[kt][3]);
    }

    for (int c = nh * 4; c < nh * 4 + 4; c++) {
        float ci[3][4], ch[3][4];
#pragma unroll
        for (int j = 0; j < 3; j++) {
            int nb = c * 24 + j * 8 + 2 * tig;
            float b0 = sBih[nb], b1 = sBih[nb + 1];
            ci[j][0] = b0; ci[j][1] = b1; ci[j][2] = b0; ci[j][3] = b1;
            float d0 = sBhh[nb], d1 = sBhh[nb + 1];
            ch[j][0] = d0; ch[j][1] = d1; ch[j][2] = d0; ch[j][3] = d1;
        }
#pragma unroll
        for (int kt = 0; kt < 4; kt++) {
#pragma unroll
            for (int j = 0; j < 3; j++) {
                int o = (c * 24 + j * 8 + gid) * WST + kt * 4 + tig;
                uint2 wA = sW[0 * 192 * WST + o];
                uint2 wB = sW[1 * 192 * WST + o];
                uint2 wC = sW[2 * 192 * WST + o];
                uint2 wD = sW[3 * 192 * WST + o];
                mma16816(ci[j], aXh[kt], wA.x, wA.y);
                mma16816(ci[j], aXl[kt], wA.x, wA.y);
                mma16816(ci[j], aXh[kt], wB.x, wB.y);
                mma16816(ch[j], aHh[kt], wC.x, wC.y);
                mma16816(ch[j], aHl[kt], wC.x, wC.y);
                mma16816(ch[j], aHh[kt], wD.x, wD.y);
            }
        }
#pragma unroll
        for (int half = 0; half < 2; half++) {
            int lrow = (half == 0) ? row0 : row1;
            int l = lbase + lrow;
            int ri = half * 2;
            int ubase = c * 8 + 2 * tig;
            float hold0 = sH[lrow * PADX + ubase];
            float hold1 = sH[lrow * PADX + ubase + 1];
            float r0 = fsigm(ci[0][ri] + ch[0][ri]);
            float z0 = fsigm(ci[1][ri] + ch[1][ri]);
            float n0 = ftanh(ci[2][ri] + r0 * ch[2][ri]);
            float hn0 = (1.f - z0) * n0 + z0 * hold0;
            float r1 = fsigm(ci[0][ri + 1] + ch[0][ri + 1]);
            float z1 = fsigm(ci[1][ri + 1] + ch[1][ri + 1]);
            float n1 = ftanh(ci[2][ri + 1] + r1 * ch[2][ri + 1]);
            float hn1 = (1.f - z1) * n1 + z1 * hold1;
            if (l < NLINK)
                *(float2*)(g_link_state + l * 64 + ubase) = make_float2(hn0, hn1);
        }
    }
}

// ---------------------------------------------------------------------------
// Embedding
// ---------------------------------------------------------------------------
template <int TARGET>
__global__ void embed_kernel(const float* __restrict__ x,
                             const float* __restrict__ w1, const float* __restrict__ b1,
                             const float* __restrict__ w2, const float* __restrict__ b2,
                             int n) {
    __shared__ float sWm[64 * 64];
    __shared__ float sw1[64], sb1[64], sb2[64];
    __shared__ float sh1[4][64];
    float* st = (TARGET == 0) ? g_path_state : g_link_state;
    int tid = threadIdx.x;
    for (int i = tid; i < 4096; i += 256) {
        int j = i >> 6, k = i & 63;
        sWm[k * 64 + j] = w2[i];
    }
    if (tid < 64) { sw1[tid] = w1[tid]; sb1[tid] = b1[tid]; sb2[tid] = b2[tid]; }
    __syncthreads();
    int g = tid >> 6, d = tid & 63;
    for (int base = blockIdx.x * 4; base < n; base += gridDim.x * 4) {
        int p = base + g;
        float h1 = 0.0f;
        if (p < n) {
            float t = x[p];
            h1 = fmaxf(t * sw1[d] + sb1[d], 0.0f);
        }
        sh1[g][d] = h1;
        groupbar(g);
        float acc = sb2[d];
#pragma unroll 8
        for (int k = 0; k < 64; k++) acc += sh1[g][k] * sWm[k * 64 + d];
        if (p < n) st[p * 64 + d] = fmaxf(acc, 0.0f);
        groupbar(g);
    }
}

// ---------------------------------------------------------------------------
// Link aggregation
// ---------------------------------------------------------------------------
__global__ void agg_kernel(const int* __restrict__ p2l) {
    __shared__ int s_pi[4][NDEG], s_pos[4][NDEG];
    int tid = threadIdx.x;
    int g = tid >> 6, d = tid & 63;
    for (int base = blockIdx.x * 4; base < NLINK; base += gridDim.x * 4) {
        int l = base + g;
        if (l < NLINK && d < NDEG) {
            s_pi[g][d]  = p2l[(l * NDEG + d) * 2];
            s_pos[g][d] = p2l[(l * NDEG + d) * 2 + 1];
        }
        groupbar(g);
        if (l < NLINK) {
            float vmin = INFINITY, vmax = -INFINITY, vsum = 0.0f;
            int cnt = 0;
            for (int e = 0; e < NDEG; e++) {
                int pi = s_pi[g][e];
                if (pi < 0) continue;
                cnt++;
                float v = g_pss[(pi * 9 + s_pos[g][e]) * 64 + d];
                vmin = fminf(vmin, v);
                vmax = fmaxf(vmax, v);
                vsum += v;
            }
            float mean = vsum / (float)(cnt > 0 ? cnt : 1);
            g_agg[l * 256 + d]        = vmin;
            g_agg[l * 256 + 64 + d]   = vmax;
            g_agg[l * 256 + 128 + d]  = vsum;
            g_agg[l * 256 + 192 + d]  = mean;
        }
        groupbar(g);
    }
}

// ---------------------------------------------------------------------------
// Grouped batched matvec + relu. SRC/DST: 0=g_agg,1=g_t1,2=g_t2,3=g_pa.
// ---------------------------------------------------------------------------
__device__ __forceinline__ float* buf_sel(int s) {
    if (s == 0) return g_agg;
    if (s == 1) return g_t1;
    if (s == 2) return g_t2;
    return g_pa;
}

template <int IN, int OUT, int NL, int GR, int SRC, int DST>
__global__ void matvec_relu(const float* __restrict__ W,
                            const float* __restrict__ b, int n) {
    extern __shared__ float sm[];
    float* sWT = sm;
    float* sb  = sWT + IN * OUT;
    float* sin = sb + OUT;
    const float* in = buf_sel(SRC);
    float* out = buf_sel(DST);
    int tid = threadIdx.x;
    const int NTH = OUT * GR;
    for (int i = tid; i < IN * OUT; i += NTH) {
        int j = i / IN, k = i % IN;
        sWT[k * OUT + j] = W[i];
    }
    if (tid < OUT) sb[tid] = b[tid];
    __syncthreads();
    int g = tid / OUT, j = tid % OUT;
    float* gin = sin + g * NL * IN;
    for (int l0 = (blockIdx.x * GR + g) * NL; l0 < n; l0 += gridDim.x * GR * NL) {
        for (int i = j; i < NL * IN; i += OUT) {
            int ll = l0 + i / IN;
            gin[i] = (ll < n) ? in[ll * IN + (i % IN)] : 0.0f;
        }
        asm volatile("bar.sync %0, %1;" :: "r"(g + 1), "r"(OUT) : "memory");
        float acc[NL];
#pragma unroll
        for (int q = 0; q < NL; q++) acc[q] = sb[j];
#pragma unroll 4
        for (int k = 0; k < IN; k++) {
            float w = sWT[k * OUT + j];
#pragma unroll
            for (int q = 0; q < NL; q++) acc[q] += gin[q * IN + k] * w;
        }
#pragma unroll
        for (int q = 0; q < NL; q++) {
            int ll = l0 + q;
            if (ll < n) out[ll * OUT + j] = fmaxf(acc[q], 0.0f);
        }
        asm volatile("bar.sync %0, %1;" :: "r"(g + 1), "r"(OUT) : "memory");
    }
}

__global__ void copy_out_kernel(float* __restrict__ out, int out_size) {
    const int n1 = NPATH * DS;
    const int n2 = n1 + NLINK * DS;
    for (int i = blockIdx.x * blockDim.x + threadIdx.x; i < out_size;
         i += gridDim.x * blockDim.x) {
        float v = 0.0f;
        if (i < n1) v = g_path_state[i];
        else if (i < n2) v = g_link_state[i - n1];
        out[i] = v;
    }
}

extern "C" void kernel_launch(void* const* d_in, const int* in_sizes, int n_in,
                              void* d_out, int out_size) {
    const float* traffic   = (const float*)d_in[0];
    const float* capacity  = (const float*)d_in[1];
    const int*   l2p       = (const int*)d_in[2];
    const int*   p2l       = (const int*)d_in[3];
    const float* pe_w1 = (const float*)d_in[4];
    const float* pe_b1 = (const float*)d_in[5];
    const float* pe_w2 = (const float*)d_in[6];
    const float* pe_b2 = (const float*)d_in[7];
    const float* le_w1 = (const float*)d_in[8];
    const float* le_b1 = (const float*)d_in[9];
    const float* le_w2 = (const float*)d_in[10];
    const float* le_b2 = (const float*)d_in[11];
    const float* gru_wih = (const float*)d_in[12];
    const float* gru_whh = (const float*)d_in[13];
    const float* gru_bih = (const float*)d_in[14];
    const float* gru_bhh = (const float*)d_in[15];
    const float* cell_wih = (const float*)d_in[16];
    const float* cell_whh = (const float*)d_in[17];
    const float* cell_bih = (const float*)d_in[18];
    const float* cell_bhh = (const float*)d_in[19];
    const float* am_w1 = (const float*)d_in[20];
    const float* am_b1 = (const float*)d_in[21];
    const float* am_w2 = (const float*)d_in[22];
    const float* am_b2 = (const float*)d_in[23];
    const float* am_w3 = (const float*)d_in[24];
    const float* am_b3 = (const float*)d_in[25];

    const size_t smem_mma  = (size_t)(4 * 192 * WST) * 8 + (size_t)(128 * PADX) * 4
                           + (size_t)(2 * 128 * PADK) * 2 + (size_t)(2 * 192) * 4
                           + (size_t)(128 * TMAX) * 4;
    const size_t smem_link = (size_t)(4 * 192 * WST) * 8 + (size_t)(2 * 128 * PADX) * 4
                           + (size_t)(2 * 192) * 4;
    const size_t smem_l1 = (size_t)(256 * 128 + 128 + 4 * 8 * 256) * 4;
    const size_t smem_l2 = (size_t)(128 * 128 + 128 + 4 * 8 * 128) * 4;
    const size_t smem_l3 = (size_t)(128 * 64 + 64 + 8 * 8 * 128) * 4;

    cudaFuncSetAttribute(gru_path_mma, cudaFuncAttributeMaxDynamicSharedMemorySize, (int)smem_mma);
    cudaFuncSetAttribute(gru_link_mma, cudaFuncAttributeMaxDynamicSharedMemorySize, (int)smem_link);
    cudaFuncSetAttribute(matvec_relu<256, 128, 8, 4, 0, 1>, cudaFuncAttributeMaxDynamicSharedMemorySize, (int)smem_l1);
    cudaFuncSetAttribute(matvec_relu<128, 128, 8, 4, 1, 2>, cudaFuncAttributeMaxDynamicSharedMemorySize, (int)smem_l2);
    cudaFuncSetAttribute(matvec_relu<128, 64, 8, 8, 2, 3>,  cudaFuncAttributeMaxDynamicSharedMemorySize, (int)smem_l3);

    prep_weights<<<28, 256>>>(gru_wih, gru_whh, gru_bih, gru_bhh,
                              cell_wih, cell_whh, cell_bih, cell_bhh);
    embed_kernel<0><<<1024, 256>>>(traffic, pe_w1, pe_b1, pe_w2, pe_b2, NPATH);
    embed_kernel<1><<<512, 256>>>(capacity, le_w1, le_b1, le_w2, le_b2, NLINK);

    const int gru_blocks  = (NPATH + 127) / 128;   // 782
    const int link_blocks = (NLINK + 127) / 128;   // 157

    for (int it = 0; it < NITERS; it++) {
        gru_path_mma<<<gru_blocks, 512, smem_mma>>>(l2p);
        agg_kernel<<<1024, 256>>>(p2l);
        matvec_relu<256, 128, 8, 4, 0, 1><<<625, 512, smem_l1>>>(am_w1, am_b1, NLINK);
        matvec_relu<128, 128, 8, 4, 1, 2><<<625, 512, smem_l2>>>(am_w2, am_b2, NLINK);
        matvec_relu<128, 64, 8, 8, 2, 3><<<313, 512, smem_l3>>>(am_w3, am_b3, NLINK);
        gru_link_mma<<<link_blocks, 512, smem_link>>>();
    }

    copy_out_kernel<<<4096, 256>>>((float*)d_out, out_size);
}

// round 11
// speedup vs baseline: 2.2424x; 1.0602x over previous
#include <cuda_runtime.h>
#include <cuda_bf16.h>
#include <math.h>
#include <stdint.h>

#define NPATH 100000
#define NLINK 20000
#define TMAX 8
#define NDEG 48
#define DS 64
#define NITERS 4
#define PADK 72   // bf16 H-tile row stride
#define PADX 68   // fp32 X/H-tile row stride (16B-aligned rows)
#define WST 20    // packed-weight row stride in uint2

// Persistent scratch: uninitialized __device__ globals.
__device__ float g_path_state[NPATH * DS];
__device__ float g_link_state[NLINK * DS];
__device__ float g_pss[NPATH * (TMAX + 1) * DS];
__device__ float g_agg[NLINK * 4 * DS];
__device__ float g_t1[NLINK * 128];
__device__ float g_t2[NLINK * 128];
__device__ float g_pa[NLINK * DS];
// Packed GRU weights (path + cell): gate-permuted, bf16 hi/lo, frag-ready uint2.
__device__ uint2 g_wp[4 * 192 * WST];    // path GRU
__device__ uint2 g_wpc[4 * 192 * WST];   // link (cell) GRU
__device__ float g_bih_p[192], g_bhh_p[192];
__device__ float g_bihc_p[192], g_bhhc_p[192];

__device__ __forceinline__ void groupbar(int g) {
    asm volatile("bar.sync %0, 64;" :: "r"(g + 1) : "memory");
}
__device__ __forceinline__ float fsigm(float x) {
    return __fdividef(1.0f, 1.0f + __expf(-x));
}
__device__ __forceinline__ float ftanh(float x) {
    x = fminf(fmaxf(x, -15.0f), 15.0f);
    float e = __expf(-2.0f * x);
    return __fdividef(1.0f - e, 1.0f + e);
}

__device__ __forceinline__ uint32_t packbf(float f0, float f1) {
    __nv_bfloat162 v = __floats2bfloat162_rn(f0, f1);
    return *reinterpret_cast<uint32_t*>(&v);
}
// split float2 -> bf16x2 hi + bf16x2 lo
__device__ __forceinline__ void split2(float2 v, uint32_t& hi, uint32_t& lo) {
    __nv_bfloat162 h = __floats2bfloat162_rn(v.x, v.y);
    hi = *reinterpret_cast<uint32_t*>(&h);
    lo = packbf(v.x - __bfloat162float(h.x), v.y - __bfloat162float(h.y));
}

__device__ __forceinline__ void mma16816(float* c, const uint32_t* a, uint32_t b0, uint32_t b1) {
    asm("mma.sync.aligned.m16n8k16.row.col.f32.bf16.bf16.f32 "
        "{%0,%1,%2,%3}, {%4,%5,%6,%7}, {%8,%9}, {%0,%1,%2,%3};"
        : "+f"(c[0]), "+f"(c[1]), "+f"(c[2]), "+f"(c[3])
        : "r"(a[0]), "r"(a[1]), "r"(a[2]), "r"(a[3]), "r"(b0), "r"(b1));
}

// ---------------------------------------------------------------------------
// Weight prep (path + cell): gate-permute, bf16 hi/lo split, frag-pack.
// ---------------------------------------------------------------------------
__device__ __forceinline__ void pack_w(const float* __restrict__ wih,
                                       const float* __restrict__ whh,
                                       uint2* dst, int i) {
    int r = i >> 4, rem2 = i & 15;
    int kt = rem2 >> 2, tig = rem2 & 3;
    int c = r / 24, rr = r % 24, gate = rr >> 3, u = rr & 7;
    int ro = gate * 64 + c * 8 + u;
    int k0 = kt * 16 + 2 * tig;
    const float* wi = wih + ro * 64;
    const float* wh = whh + ro * 64;
    float fi[4] = { wi[k0], wi[k0 + 1], wi[k0 + 8], wi[k0 + 9] };
    float fh[4] = { wh[k0], wh[k0 + 1], wh[k0 + 8], wh[k0 + 9] };
    float hi_i[4], hi_h[4];
#pragma unroll
    for (int q = 0; q < 4; q++) {
        hi_i[q] = __bfloat162float(__float2bfloat16(fi[q]));
        hi_h[q] = __bfloat162float(__float2bfloat16(fh[q]));
    }
    int o = r * WST + kt * 4 + tig;
    uint2 v;
    v.x = packbf(fi[0], fi[1]);                     v.y = packbf(fi[2], fi[3]);
    dst[0 * 192 * WST + o] = v;
    v.x = packbf(fi[0] - hi_i[0], fi[1] - hi_i[1]); v.y = packbf(fi[2] - hi_i[2], fi[3] - hi_i[3]);
    dst[1 * 192 * WST + o] = v;
    v.x = packbf(fh[0], fh[1]);                     v.y = packbf(fh[2], fh[3]);
    dst[2 * 192 * WST + o] = v;
    v.x = packbf(fh[0] - hi_h[0], fh[1] - hi_h[1]); v.y = packbf(fh[2] - hi_h[2], fh[3] - hi_h[3]);
    dst[3 * 192 * WST + o] = v;
}

__global__ void prep_weights(const float* __restrict__ wih, const float* __restrict__ whh,
                             const float* __restrict__ bih, const float* __restrict__ bhh,
                             const float* __restrict__ cwih, const float* __restrict__ cwhh,
                             const float* __restrict__ cbih, const float* __restrict__ cbhh) {
    int i = blockIdx.x * blockDim.x + threadIdx.x;
    if (i < 192) {
        int c = i / 24, rem = i % 24, gate = rem >> 3, u = rem & 7;
        int ro = gate * 64 + c * 8 + u;
        g_bih_p[i] = bih[ro];   g_bhh_p[i] = bhh[ro];
        g_bihc_p[i] = cbih[ro]; g_bhhc_p[i] = cbhh[ro];
    }
    if (i < 3072) pack_w(wih, whh, g_wp, i);
    else if (i >= 4096 && i < 7168) pack_w(cwih, cwhh, g_wpc, i - 4096);
}

// ---------------------------------------------------------------------------
// cp.async gather of one timestep's x rows into fp32 X tile (zero-fill invalid)
// ---------------------------------------------------------------------------
__device__ __forceinline__ void gather_async(float* sX, const int* sIdx, int t, int tid) {
    for (int i = tid; i < 128 * 16; i += 512) {
        int pl = i >> 4, q = i & 15;
        int idx = sIdx[pl * TMAX + t];
        const float* src = g_link_state + (idx >= 0 ? idx : 0) * 64 + q * 4;
        uint32_t dst = (uint32_t)__cvta_generic_to_shared(sX + pl * PADX + q * 4);
        int sz = (idx >= 0) ? 16 : 0;
        asm volatile("cp.async.ca.shared.global [%0], [%1], 16, %2;"
                     :: "r"(dst), "l"(src), "r"(sz) : "memory");
    }
}

// ---------------------------------------------------------------------------
// FUSED path GRU, N-split, cp.async-pipelined. 512 threads = 16 warps.
// Warp w: M-rows [16*(w&7), +16), N-half (w>>3) = chunks [4*nh, +4).
// ---------------------------------------------------------------------------
__global__ void __launch_bounds__(512, 1) gru_path_mma(const int* __restrict__ l2p) {
    extern __shared__ __align__(16) char smraw[];
    uint2* sW          = (uint2*)smraw;                       // [4][192][WST]
    float* sX          = (float*)(sW + 4 * 192 * WST);        // [128][PADX] fp32
    __nv_bfloat16* sHh = (__nv_bfloat16*)(sX + 128 * PADX);   // [128][PADK]
    __nv_bfloat16* sHl = sHh + 128 * PADK;
    float* sBih        = (float*)(sHl + 128 * PADK);          // [192]
    float* sBhh        = sBih + 192;
    int*   sIdx        = (int*)(sBhh + 192);                  // [128][TMAX]

    int tid = threadIdx.x;
    int pbase = blockIdx.x * 128;

    // stage indices first (gather depends on them)
    for (int i = tid; i < 128 * TMAX; i += 512) {
        int pl = i / TMAX, tt = i % TMAX;
        int p = pbase + pl;
        sIdx[pl * TMAX + tt] = (p < NPATH) ? l2p[p * TMAX + tt] : -1;
    }
    __syncthreads();

    // issue gather(0) while staging everything else
    gather_async(sX, sIdx, 0, tid);
    asm volatile("cp.async.commit_group;" ::: "memory");

    for (int i = tid; i < 4 * 192 * WST; i += 512) sW[i] = g_wp[i];
    if (tid < 192) { sBih[tid] = g_bih_p[tid]; sBhh[tid] = g_bhh_p[tid]; }

    for (int i = tid; i < 128 * 64; i += 512) {
        int pl = i >> 6, k = i & 63;
        int p = pbase + pl;
        float hv = 0.f;
        if (p < NPATH) {
            hv = g_path_state[p * 64 + k];
            g_pss[p * 576 + k] = hv;
        }
        __nv_bfloat16 hh = __float2bfloat16(hv);
        sHh[pl * PADK + k] = hh;
        sHl[pl * PADK + k] = __float2bfloat16(hv - __bfloat162float(hh));
    }
    asm volatile("cp.async.wait_group 0;" ::: "memory");
    __syncthreads();

    int warp = tid >> 5, lane = tid & 31;
    int mw = warp & 7, nh = warp >> 3;
    int gid = lane >> 2, tig = lane & 3;
    int row0 = mw * 16 + gid;
    int row1 = row0 + 8;

    for (int t = 0; t < TMAX; t++) {
        // build A fragments: X from fp32 tile (split in regs), H from bf16 tiles
        uint32_t aXh[4][4], aXl[4][4], aHh[4][4], aHl[4][4];
#pragma unroll
        for (int kt = 0; kt < 4; kt++) {
            int kb = kt * 16 + 2 * tig;
            float2 v;
            v = *(float2*)(sX + row0 * PADX + kb);     split2(v, aXh[kt][0], aXl[kt][0]);
            v = *(float2*)(sX + row1 * PADX + kb);     split2(v, aXh[kt][1], aXl[kt][1]);
            v = *(float2*)(sX + row0 * PADX + kb + 8); split2(v, aXh[kt][2], aXl[kt][2]);
            v = *(float2*)(sX + row1 * PADX + kb + 8); split2(v, aXh[kt][3], aXl[kt][3]);
            const __nv_bfloat16 *r0p, *r1p;
            r0p = sHh + row0 * PADK + kb; r1p = sHh + row1 * PADK + kb;
            aHh[kt][0] = *(const uint32_t*)(r0p);
            aHh[kt][1] = *(const uint32_t*)(r1p);
            aHh[kt][2] = *(const uint32_t*)(r0p + 8);
            aHh[kt][3] = *(const uint32_t*)(r1p + 8);
            r0p = sHl + row0 * PADK + kb; r1p = sHl + row1 * PADK + kb;
            aHl[kt][0] = *(const uint32_t*)(r0p);
            aHl[kt][1] = *(const uint32_t*)(r1p);
            aHl[kt][2] = *(const uint32_t*)(r0p + 8);
            aHl[kt][3] = *(const uint32_t*)(r1p + 8);
        }
        __syncthreads();   // frag reads done: X tile free for prefetch, H tiles free for epilogue

        if (t + 1 < TMAX) gather_async(sX, sIdx, t + 1, tid);
        asm volatile("cp.async.commit_group;" ::: "memory");

        for (int c = nh * 4; c < nh * 4 + 4; c++) {
            float ci[3][4], ch[3][4];
#pragma unroll
            for (int j = 0; j < 3; j++) {
                int nb = c * 24 + j * 8 + 2 * tig;
                float b0 = sBih[nb], b1 = sBih[nb + 1];
                ci[j][0] = b0; ci[j][1] = b1; ci[j][2] = b0; ci[j][3] = b1;
                float d0 = sBhh[nb], d1 = sBhh[nb + 1];
                ch[j][0] = d0; ch[j][1] = d1; ch[j][2] = d0; ch[j][3] = d1;
            }
#pragma unroll
            for (int kt = 0; kt < 4; kt++) {
#pragma unroll
                for (int j = 0; j < 3; j++) {
                    int o = (c * 24 + j * 8 + gid) * WST + kt * 4 + tig;
                    uint2 wA = sW[0 * 192 * WST + o];
                    uint2 wB = sW[1 * 192 * WST + o];
                    uint2 wC = sW[2 * 192 * WST + o];
                    uint2 wD = sW[3 * 192 * WST + o];
                    mma16816(ci[j], aXh[kt], wA.x, wA.y);
                    mma16816(ci[j], aXl[kt], wA.x, wA.y);
                    mma16816(ci[j], aXh[kt], wB.x, wB.y);
                    mma16816(ch[j], aHh[kt], wC.x, wC.y);
                    mma16816(ch[j], aHl[kt], wC.x, wC.y);
                    mma16816(ch[j], aHh[kt], wD.x, wD.y);
                }
            }
#pragma unroll
            for (int half = 0; half < 2; half++) {
                int lrow = (half == 0) ? row0 : row1;
                int p = pbase + lrow;
                int valid = sIdx[lrow * TMAX + t] >= 0;
                int ri = half * 2;
                int ubase = c * 8 + 2 * tig;
                uint32_t hhp = *(uint32_t*)(sHh + lrow * PADK + ubase);
                uint32_t hlp = *(uint32_t*)(sHl + lrow * PADK + ubase);
                __nv_bfloat162 hh2 = *(__nv_bfloat162*)&hhp;
                __nv_bfloat162 hl2 = *(__nv_bfloat162*)&hlp;
                float hold0 = __bfloat162float(hh2.x) + __bfloat162float(hl2.x);
                float hold1 = __bfloat162float(hh2.y) + __bfloat162float(hl2.y);
                float r0 = fsigm(ci[0][ri] + ch[0][ri]);
                float z0 = fsigm(ci[1][ri] + ch[1][ri]);
                float n0 = ftanh(ci[2][ri] + r0 * ch[2][ri]);
                float hn0 = valid ? ((1.f - z0) * n0 + z0 * hold0) : hold0;
                float r1 = fsigm(ci[0][ri + 1] + ch[0][ri + 1]);
                float z1 = fsigm(ci[1][ri + 1] + ch[1][ri + 1]);
                float n1 = ftanh(ci[2][ri + 1] + r1 * ch[2][ri + 1]);
                float hn1 = valid ? ((1.f - z1) * n1 + z1 * hold1) : hold1;
                float h0f = __bfloat162float(__float2bfloat16(hn0));
                float h1f = __bfloat162float(__float2bfloat16(hn1));
                *(uint32_t*)(sHh + lrow * PADK + ubase) = packbf(hn0, hn1);
                *(uint32_t*)(sHl + lrow * PADK + ubase) = packbf(hn0 - h0f, hn1 - h1f);
                if (p < NPATH) {
                    float2 o2 = make_float2(valid ? hn0 : 0.f, valid ? hn1 : 0.f);
                    *(float2*)(g_pss + p * 576 + (t + 1) * 64 + ubase) = o2;
                }
            }
        }
        asm volatile("cp.async.wait_group 0;" ::: "memory");
        __syncthreads();   // epilogue h-writes + prefetched X visible
    }

    for (int i = tid; i < 128 * 64; i += 512) {
        int pl = i >> 6, k = i & 63;
        int p = pbase + pl;
        if (p < NPATH)
            g_path_state[p * 64 + k] =
                __bfloat162float(sHh[pl * PADK + k]) + __bfloat162float(sHl[pl * PADK + k]);
    }
}

// ---------------------------------------------------------------------------
// Link GRU via MMA: one step, dense. x = g_pa, h = g_link_state (in/out).
// ---------------------------------------------------------------------------
__global__ void __launch_bounds__(512, 1) gru_link_mma() {
    extern __shared__ __align__(16) char smraw[];
    uint2* sW   = (uint2*)smraw;                      // [4][192][WST]
    float* sX   = (float*)(sW + 4 * 192 * WST);       // [128][PADX]
    float* sH   = sX + 128 * PADX;                    // [128][PADX]
    float* sBih = sH + 128 * PADX;                    // [192]
    float* sBhh = sBih + 192;

    int tid = threadIdx.x;
    int lbase = blockIdx.x * 128;

    for (int i = tid; i < 4 * 192 * WST; i += 512) sW[i] = g_wpc[i];
    if (tid < 192) { sBih[tid] = g_bihc_p[tid]; sBhh[tid] = g_bhhc_p[tid]; }
    for (int i = tid; i < 128 * 64; i += 512) {
        int pl = i >> 6, k = i & 63;
        int l = lbase + pl;
        sX[pl * PADX + k] = (l < NLINK) ? g_pa[l * 64 + k] : 0.f;
        sH[pl * PADX + k] = (l < NLINK) ? g_link_state[l * 64 + k] : 0.f;
    }
    __syncthreads();

    int warp = tid >> 5, lane = tid & 31;
    int mw = warp & 7, nh = warp >> 3;
    int gid = lane >> 2, tig = lane & 3;
    int row0 = mw * 16 + gid;
    int row1 = row0 + 8;

    uint32_t aXh[4][4], aXl[4][4], aHh[4][4], aHl[4][4];
#pragma unroll
    for (int kt = 0; kt < 4; kt++) {
        int kb = kt * 16 + 2 * tig;
        float2 v;
        v = *(float2*)(sX + row0 * PADX + kb);     split2(v, aXh[kt][0], aXl[kt][0]);
        v = *(float2*)(sX + row1 * PADX + kb);     split2(v, aXh[kt][1], aXl[kt][1]);
        v = *(float2*)(sX + row0 * PADX + kb + 8); split2(v, aXh[kt][2], aXl[kt][2]);
        v = *(float2*)(sX + row1 * PADX + kb + 8); split2(v, aXh[kt][3], aXl[kt][3]);
        v = *(float2*)(sH + row0 * PADX + kb);     split2(v, aHh[kt][0], aHl[kt][0]);
        v = *(float2*)(sH + row1 * PADX + kb);     split2(v, aHh[kt][1], aHl[kt][1]);
        v = *(float2*)(sH + row0 * PADX + kb + 8); split2(v, aHh[kt][2], aHl[kt][2]);
        v = *(float2*)(sH + row1 * PADX + kb + 8); split2(v, aHh[kt][3], aHl[kt][3]);
    }

    for (int c = nh * 4; c < nh * 4 + 4; c++) {
        float ci[3][4], ch[3][4];
#pragma unroll
        for (int j = 0; j < 3; j++) {
            int nb = c * 24 + j * 8 + 2 * tig;
            float b0 = sBih[nb], b1 = sBih[nb + 1];
            ci[j][0] = b0; ci[j][1] = b1; ci[j][2] = b0; ci[j][3] = b1;
            float d0 = sBhh[nb], d1 = sBhh[nb + 1];
            ch[j][0] = d0; ch[j][1] = d1; ch[j][2] = d0; ch[j][3] = d1;
        }
#pragma unroll
        for (int kt = 0; kt < 4; kt++) {
#pragma unroll
            for (int j = 0; j < 3; j++) {
                int o = (c * 24 + j * 8 + gid) * WST + kt * 4 + tig;
                uint2 wA = sW[0 * 192 * WST + o];
                uint2 wB = sW[1 * 192 * WST + o];
                uint2 wC = sW[2 * 192 * WST + o];
                uint2 wD = sW[3 * 192 * WST + o];
                mma16816(ci[j], aXh[kt], wA.x, wA.y);
                mma16816(ci[j], aXl[kt], wA.x, wA.y);
                mma16816(ci[j], aXh[kt], wB.x, wB.y);
                mma16816(ch[j], aHh[kt], wC.x, wC.y);
                mma16816(ch[j], aHl[kt], wC.x, wC.y);
                mma16816(ch[j], aHh[kt], wD.x, wD.y);
            }
        }
#pragma unroll
        for (int half = 0; half < 2; half++) {
            int lrow = (half == 0) ? row0 : row1;
            int l = lbase + lrow;
            int ri = half * 2;
            int ubase = c * 8 + 2 * tig;
            float hold0 = sH[lrow * PADX + ubase];
            float hold1 = sH[lrow * PADX + ubase + 1];
            float r0 = fsigm(ci[0][ri] + ch[0][ri]);
            float z0 = fsigm(ci[1][ri] + ch[1][ri]);
            float n0 = ftanh(ci[2][ri] + r0 * ch[2][ri]);
            float hn0 = (1.f - z0) * n0 + z0 * hold0;
            float r1 = fsigm(ci[0][ri + 1] + ch[0][ri + 1]);
            float z1 = fsigm(ci[1][ri + 1] + ch[1][ri + 1]);
            float n1 = ftanh(ci[2][ri + 1] + r1 * ch[2][ri + 1]);
            float hn1 = (1.f - z1) * n1 + z1 * hold1;
            if (l < NLINK)
                *(float2*)(g_link_state + l * 64 + ubase) = make_float2(hn0, hn1);
        }
    }
}

// ---------------------------------------------------------------------------
// Embedding
// ---------------------------------------------------------------------------
template <int TARGET>
__global__ void embed_kernel(const float* __restrict__ x,
                             const float* __restrict__ w1, const float* __restrict__ b1,
                             const float* __restrict__ w2, const float* __restrict__ b2,
                             int n) {
    __shared__ float sWm[64 * 64];
    __shared__ float sw1[64], sb1[64], sb2[64];
    __shared__ float sh1[4][64];
    float* st = (TARGET == 0) ? g_path_state : g_link_state;
    int tid = threadIdx.x;
    for (int i = tid; i < 4096; i += 256) {
        int j = i >> 6, k = i & 63;
        sWm[k * 64 + j] = w2[i];
    }
    if (tid < 64) { sw1[tid] = w1[tid]; sb1[tid] = b1[tid]; sb2[tid] = b2[tid]; }
    __syncthreads();
    int g = tid >> 6, d = tid & 63;
    for (int base = blockIdx.x * 4; base < n; base += gridDim.x * 4) {
        int p = base + g;
        float h1 = 0.0f;
        if (p < n) {
            float t = x[p];
            h1 = fmaxf(t * sw1[d] + sb1[d], 0.0f);
        }
        sh1[g][d] = h1;
        groupbar(g);
        float acc = sb2[d];
#pragma unroll 8
        for (int k = 0; k < 64; k++) acc += sh1[g][k] * sWm[k * 64 + d];
        if (p < n) st[p * 64 + d] = fmaxf(acc, 0.0f);
        groupbar(g);
    }
}

// ---------------------------------------------------------------------------
// Link aggregation (dual accumulator chains for MLP)
// ---------------------------------------------------------------------------
__global__ void agg_kernel(const int* __restrict__ p2l) {
    __shared__ int s_pi[4][NDEG], s_pos[4][NDEG];
    int tid = threadIdx.x;
    int g = tid >> 6, d = tid & 63;
    for (int base = blockIdx.x * 4; base < NLINK; base += gridDim.x * 4) {
        int l = base + g;
        if (l < NLINK && d < NDEG) {
            s_pi[g][d]  = p2l[(l * NDEG + d) * 2];
            s_pos[g][d] = p2l[(l * NDEG + d) * 2 + 1];
        }
        groupbar(g);
        if (l < NLINK) {
            float mn0 = INFINITY, mx0 = -INFINITY, sm0 = 0.0f;
            float mn1 = INFINITY, mx1 = -INFINITY, sm1 = 0.0f;
            int c0 = 0, c1 = 0;
#pragma unroll 4
            for (int e = 0; e < NDEG; e += 2) {
                int pi0 = s_pi[g][e];
                int pi1 = s_pi[g][e + 1];
                if (pi0 >= 0) {
                    float v = g_pss[(pi0 * 9 + s_pos[g][e]) * 64 + d];
                    c0++;
                    mn0 = fminf(mn0, v); mx0 = fmaxf(mx0, v); sm0 += v;
                }
                if (pi1 >= 0) {
                    float v = g_pss[(pi1 * 9 + s_pos[g][e + 1]) * 64 + d];
                    c1++;
                    mn1 = fminf(mn1, v); mx1 = fmaxf(mx1, v); sm1 += v;
                }
            }
            float vmin = fminf(mn0, mn1);
            float vmax = fmaxf(mx0, mx1);
            float vsum = sm0 + sm1;
            int cnt = c0 + c1;
            float mean = vsum / (float)(cnt > 0 ? cnt : 1);
            g_agg[l * 256 + d]        = vmin;
            g_agg[l * 256 + 64 + d]   = vmax;
            g_agg[l * 256 + 128 + d]  = vsum;
            g_agg[l * 256 + 192 + d]  = mean;
        }
        groupbar(g);
    }
}

// ---------------------------------------------------------------------------
// Grouped batched matvec + relu, float4 inner loop.
// SRC/DST: 0=g_agg,1=g_t1,2=g_t2,3=g_pa.
// ---------------------------------------------------------------------------
__device__ __forceinline__ float* buf_sel(int s) {
    if (s == 0) return g_agg;
    if (s == 1) return g_t1;
    if (s == 2) return g_t2;
    return g_pa;
}

template <int IN, int OUT, int NL, int GR, int SRC, int DST>
__global__ void __launch_bounds__(OUT * GR) matvec_relu(const float* __restrict__ W,
                                                        const float* __restrict__ b, int n) {
    extern __shared__ float sm[];
    float* sWT = sm;                 // [IN][OUT] (k-major)
    float* sb  = sWT + IN * OUT;     // OUT
    float* sin = sb + OUT;           // [GR][NL*IN]
    const float* in = buf_sel(SRC);
    float* out = buf_sel(DST);
    int tid = threadIdx.x;
    const int NTH = OUT * GR;
    for (int i = tid; i < IN * OUT; i += NTH) {
        int j = i / IN, k = i % IN;
        sWT[k * OUT + j] = W[i];
    }
    if (tid < OUT) sb[tid] = b[tid];
    __syncthreads();
    int g = tid / OUT, j = tid % OUT;
    float* gin = sin + g * NL * IN;
    for (int l0 = (blockIdx.x * GR + g) * NL; l0 < n; l0 += gridDim.x * GR * NL) {
        // vectorized staging: float4 per thread
        for (int i4 = j; i4 < NL * IN / 4; i4 += OUT) {
            int i = i4 * 4;
            int ll = l0 + i / IN;
            int kk = i % IN;
            float4 v = make_float4(0.f, 0.f, 0.f, 0.f);
            if (ll < n) v = *(const float4*)(in + ll * IN + kk);
            *(float4*)(gin + i) = v;
        }
        asm volatile("bar.sync %0, %1;" :: "r"(g + 1), "r"(OUT) : "memory");
        float acc[NL];
#pragma unroll
        for (int q = 0; q < NL; q++) acc[q] = sb[j];
        for (int k = 0; k < IN; k += 4) {
            float w0 = sWT[k * OUT + j];
            float w1 = sWT[(k + 1) * OUT + j];
            float w2 = sWT[(k + 2) * OUT + j];
            float w3 = sWT[(k + 3) * OUT + j];
#pragma unroll
            for (int q = 0; q < NL; q++) {
                float4 gv = *(const float4*)(gin + q * IN + k);
                acc[q] = fmaf(gv.x, w0, acc[q]);
                acc[q] = fmaf(gv.y, w1, acc[q]);
                acc[q] = fmaf(gv.z, w2, acc[q]);
                acc[q] = fmaf(gv.w, w3, acc[q]);
            }
        }
#pragma unroll
        for (int q = 0; q < NL; q++) {
            int ll = l0 + q;
            if (ll < n) out[ll * OUT + j] = fmaxf(acc[q], 0.0f);
        }
        asm volatile("bar.sync %0, %1;" :: "r"(g + 1), "r"(OUT) : "memory");
    }
}

__global__ void copy_out_kernel(float* __restrict__ out, int out_size) {
    const int n1 = NPATH * DS;
    const int n2 = n1 + NLINK * DS;
    for (int i = blockIdx.x * blockDim.x + threadIdx.x; i < out_size;
         i += gridDim.x * blockDim.x) {
        float v = 0.0f;
        if (i < n1) v = g_path_state[i];
        else if (i < n2) v = g_link_state[i - n1];
        out[i] = v;
    }
}

extern "C" void kernel_launch(void* const* d_in, const int* in_sizes, int n_in,
                              void* d_out, int out_size) {
    const float* traffic   = (const float*)d_in[0];
    const float* capacity  = (const float*)d_in[1];
    const int*   l2p       = (const int*)d_in[2];
    const int*   p2l       = (const int*)d_in[3];
    const float* pe_w1 = (const float*)d_in[4];
    const float* pe_b1 = (const float*)d_in[5];
    const float* pe_w2 = (const float*)d_in[6];
    const float* pe_b2 = (const float*)d_in[7];
    const float* le_w1 = (const float*)d_in[8];
    const float* le_b1 = (const float*)d_in[9];
    const float* le_w2 = (const float*)d_in[10];
    const float* le_b2 = (const float*)d_in[11];
    const float* gru_wih = (const float*)d_in[12];
    const float* gru_whh = (const float*)d_in[13];
    const float* gru_bih = (const float*)d_in[14];
    const float* gru_bhh = (const float*)d_in[15];
    const float* cell_wih = (const float*)d_in[16];
    const float* cell_whh = (const float*)d_in[17];
    const float* cell_bih = (const float*)d_in[18];
    const float* cell_bhh = (const float*)d_in[19];
    const float* am_w1 = (const float*)d_in[20];
    const float* am_b1 = (const float*)d_in[21];
    const float* am_w2 = (const float*)d_in[22];
    const float* am_b2 = (const float*)d_in[23];
    const float* am_w3 = (const float*)d_in[24];
    const float* am_b3 = (const float*)d_in[25];

    const size_t smem_mma  = (size_t)(4 * 192 * WST) * 8 + (size_t)(128 * PADX) * 4
                           + (size_t)(2 * 128 * PADK) * 2 + (size_t)(2 * 192) * 4
                           + (size_t)(128 * TMAX) * 4;
    const size_t smem_link = (size_t)(4 * 192 * WST) * 8 + (size_t)(2 * 128 * PADX) * 4
                           + (size_t)(2 * 192) * 4;
    const size_t smem_l1 = (size_t)(256 * 128 + 128 + 4 * 16 * 256) * 4;   // 197120
    const size_t smem_l2 = (size_t)(128 * 128 + 128 + 4 * 16 * 128) * 4;   // 98816
    const size_t smem_l3 = (size_t)(128 * 64 + 64 + 8 * 16 * 128) * 4;     // 98560

    cudaFuncSetAttribute(gru_path_mma, cudaFuncAttributeMaxDynamicSharedMemorySize, (int)smem_mma);
    cudaFuncSetAttribute(gru_link_mma, cudaFuncAttributeMaxDynamicSharedMemorySize, (int)smem_link);
    cudaFuncSetAttribute(matvec_relu<256, 128, 16, 4, 0, 1>, cudaFuncAttributeMaxDynamicSharedMemorySize, (int)smem_l1);
    cudaFuncSetAttribute(matvec_relu<128, 128, 16, 4, 1, 2>, cudaFuncAttributeMaxDynamicSharedMemorySize, (int)smem_l2);
    cudaFuncSetAttribute(matvec_relu<128, 64, 16, 8, 2, 3>,  cudaFuncAttributeMaxDynamicSharedMemorySize, (int)smem_l3);

    prep_weights<<<28, 256>>>(gru_wih, gru_whh, gru_bih, gru_bhh,
                              cell_wih, cell_whh, cell_bih, cell_bhh);
    embed_kernel<0><<<1024, 256>>>(traffic, pe_w1, pe_b1, pe_w2, pe_b2, NPATH);
    embed_kernel<1><<<512, 256>>>(capacity, le_w1, le_b1, le_w2, le_b2, NLINK);

    const int gru_blocks  = (NPATH + 127) / 128;   // 782
    const int link_blocks = (NLINK + 127) / 128;   // 157

    for (int it = 0; it < NITERS; it++) {
        gru_path_mma<<<gru_blocks, 512, smem_mma>>>(l2p);
        agg_kernel<<<2500, 256>>>(p2l);
        matvec_relu<256, 128, 16, 4, 0, 1><<<313, 512, smem_l1>>>(am_w1, am_b1, NLINK);
        matvec_relu<128, 128, 16, 4, 1, 2><<<313, 512, smem_l2>>>(am_w2, am_b2, NLINK);
        matvec_relu<128, 64, 16, 8, 2, 3><<<157, 512, smem_l3>>>(am_w3, am_b3, NLINK);
        gru_link_mma<<<link_blocks, 512, smem_link>>>();
    }

    copy_out_kernel<<<4096, 256>>>((float*)d_out, out_size);
}